// round 1
// baseline (speedup 1.0000x reference)
#include <cuda_runtime.h>
#include <math.h>

// Problem constants
#define Bc 4
#define Sc 2048
#define Ec 1024
#define Hc 16
#define Dc 64
#define Mtot (Bc*Sc)   // 8192

// Scratch (allocation-free: __device__ globals)
__device__ float g_kp[Bc*Hc*Sc*Dc];   // [B,H,S,D]
__device__ float g_vp[Bc*Hc*Sc*Dc];
__device__ float g_qp[Bc*Hc*Sc*Dc];   // pre-scaled by 1/sqrt(D)
__device__ float g_ctx[Bc*Sc*Ec];     // [B,S,E] attention output before Wo

// ---------------------------------------------------------------------------
// GEMM: C = A[M,K] @ W[N,K]^T    (M=8192, N=1024, K=1024)
// 128x128 tile, BK=8, 256 threads, 8x8 per thread.
// MODE 0: out -> g_kp in [B,H,S,D];  MODE 1: -> g_vp;  MODE 2: -> g_qp (scaled 0.125)
// MODE 3: A = g_ctx, out -> Cout plain row-major [M,N]
// ---------------------------------------------------------------------------
template <int MODE>
__global__ __launch_bounds__(256) void gemm_kernel(
    const float* __restrict__ A, const float* __restrict__ W, float* __restrict__ Cout)
{
    const int K = 1024;
    __shared__ float As[8][128];
    __shared__ float Bs[8][128];

    const float* Ain = (MODE == 3) ? (const float*)g_ctx : A;
    float* out = (MODE == 0) ? (float*)g_kp :
                 (MODE == 1) ? (float*)g_vp :
                 (MODE == 2) ? (float*)g_qp : Cout;
    const float scale = (MODE == 2) ? 0.125f : 1.0f;

    const int bn = blockIdx.x;           // N tile (0..7)
    const int bm = blockIdx.y;           // M tile (0..63)
    const int t  = threadIdx.x;          // 0..255
    const int tx = t & 15;
    const int ty = t >> 4;
    const int m0 = bm * 128;
    const int n0 = bn * 128;

    const int lrow = t >> 1;             // 0..127
    const int lk4  = (t & 1) * 4;        // 0 or 4

    float acc[8][8];
    #pragma unroll
    for (int i = 0; i < 8; i++)
        #pragma unroll
        for (int j = 0; j < 8; j++) acc[i][j] = 0.0f;

    for (int k0 = 0; k0 < K; k0 += 8) {
        float4 av = *(const float4*)&Ain[(size_t)(m0 + lrow) * K + k0 + lk4];
        float4 bv = *(const float4*)&W  [(size_t)(n0 + lrow) * K + k0 + lk4];
        As[lk4 + 0][lrow] = av.x;  As[lk4 + 1][lrow] = av.y;
        As[lk4 + 2][lrow] = av.z;  As[lk4 + 3][lrow] = av.w;
        Bs[lk4 + 0][lrow] = bv.x;  Bs[lk4 + 1][lrow] = bv.y;
        Bs[lk4 + 2][lrow] = bv.z;  Bs[lk4 + 3][lrow] = bv.w;
        __syncthreads();

        #pragma unroll
        for (int kk = 0; kk < 8; kk++) {
            float4 a0 = *(const float4*)&As[kk][ty * 8];
            float4 a1 = *(const float4*)&As[kk][ty * 8 + 4];
            float4 b0 = *(const float4*)&Bs[kk][tx * 8];
            float4 b1 = *(const float4*)&Bs[kk][tx * 8 + 4];
            float a[8] = {a0.x, a0.y, a0.z, a0.w, a1.x, a1.y, a1.z, a1.w};
            float b[8] = {b0.x, b0.y, b0.z, b0.w, b1.x, b1.y, b1.z, b1.w};
            #pragma unroll
            for (int i = 0; i < 8; i++)
                #pragma unroll
                for (int j = 0; j < 8; j++)
                    acc[i][j] = fmaf(a[i], b[j], acc[i][j]);
        }
        __syncthreads();
    }

    if (MODE == 3) {
        #pragma unroll
        for (int i = 0; i < 8; i++) {
            int m = m0 + ty * 8 + i;
            #pragma unroll
            for (int j = 0; j < 8; j += 4) {
                int n = n0 + tx * 8 + j;
                float4 vv = make_float4(acc[i][j], acc[i][j+1], acc[i][j+2], acc[i][j+3]);
                *(float4*)&out[(size_t)m * 1024 + n] = vv;
            }
        }
    } else {
        #pragma unroll
        for (int i = 0; i < 8; i++) {
            int m = m0 + ty * 8 + i;
            int b = m >> 11;            // /2048
            int s = m & 2047;
            #pragma unroll
            for (int j = 0; j < 8; j += 4) {
                int n = n0 + tx * 8 + j;
                int h = n >> 6;
                int d = n & 63;
                float4 vv = make_float4(acc[i][j]   * scale, acc[i][j+1] * scale,
                                        acc[i][j+2] * scale, acc[i][j+3] * scale);
                *(float4*)&out[(size_t)(((b * Hc + h) * Sc) + s) * Dc + d] = vv;
            }
        }
    }
}

// ---------------------------------------------------------------------------
// Flash attention (causal), fp32. One query per thread, BM=128 queries/block,
// key tiles of 32 staged in smem. Online softmax.
// Writes context into g_ctx in [B,S,E] layout (E index = h*64+d).
// ---------------------------------------------------------------------------
__global__ __launch_bounds__(128) void attn_kernel()
{
    const int b  = blockIdx.z;
    const int h  = blockIdx.y;
    const int qb = blockIdx.x;       // 0..15
    const int tid = threadIdx.x;     // 0..127
    const int qidx = qb * 128 + tid;

    __shared__ float Ks[32][64];
    __shared__ float Vs[32][64];

    const size_t bh = (size_t)(b * Hc + h) * Sc;
    const float* qbase = g_qp + (bh + qidx) * Dc;
    const float* kbase = g_kp + bh * Dc;
    const float* vbase = g_vp + bh * Dc;

    float qreg[64];
    #pragma unroll
    for (int d = 0; d < 64; d += 4) {
        float4 v = *(const float4*)&qbase[d];
        qreg[d] = v.x; qreg[d+1] = v.y; qreg[d+2] = v.z; qreg[d+3] = v.w;
    }

    float acc[64];
    #pragma unroll
    for (int d = 0; d < 64; d++) acc[d] = 0.0f;
    float mmax = -INFINITY;
    float lsum = 0.0f;

    const int nk = qb * 128 + 128;   // keys [0, nk)

    for (int k0 = 0; k0 < nk; k0 += 32) {
        __syncthreads();
        // stage K/V tiles: 32*64 floats each = 512 float4; 4 float4 per thread
        const float4* ksrc = (const float4*)(kbase + (size_t)k0 * 64);
        const float4* vsrc = (const float4*)(vbase + (size_t)k0 * 64);
        #pragma unroll
        for (int i = 0; i < 4; i++) {
            int idx = tid + i * 128;
            ((float4*)Ks)[idx] = ksrc[idx];
            ((float4*)Vs)[idx] = vsrc[idx];
        }
        __syncthreads();

        float sc[32];
        #pragma unroll
        for (int j = 0; j < 32; j++) {
            float s = 0.0f;
            #pragma unroll
            for (int d = 0; d < 64; d += 4) {
                float4 kv = *(const float4*)&Ks[j][d];
                s = fmaf(qreg[d],   kv.x, s);
                s = fmaf(qreg[d+1], kv.y, s);
                s = fmaf(qreg[d+2], kv.z, s);
                s = fmaf(qreg[d+3], kv.w, s);
            }
            sc[j] = (k0 + j <= qidx) ? s : -1e30f;
        }

        float tmax = sc[0];
        #pragma unroll
        for (int j = 1; j < 32; j++) tmax = fmaxf(tmax, sc[j]);
        float mnew = fmaxf(mmax, tmax);
        float corr = __expf(mmax - mnew);
        lsum *= corr;
        #pragma unroll
        for (int d = 0; d < 64; d++) acc[d] *= corr;

        #pragma unroll
        for (int j = 0; j < 32; j++) {
            float p = __expf(sc[j] - mnew);
            lsum += p;
            #pragma unroll
            for (int d = 0; d < 64; d += 4) {
                float4 vv = *(const float4*)&Vs[j][d];
                acc[d]   = fmaf(p, vv.x, acc[d]);
                acc[d+1] = fmaf(p, vv.y, acc[d+1]);
                acc[d+2] = fmaf(p, vv.z, acc[d+2]);
                acc[d+3] = fmaf(p, vv.w, acc[d+3]);
            }
        }
        mmax = mnew;
    }

    const float inv = 1.0f / lsum;
    float* op = g_ctx + ((size_t)b * Sc + qidx) * Ec + h * Dc;
    #pragma unroll
    for (int d = 0; d < 64; d += 4) {
        float4 vv = make_float4(acc[d] * inv, acc[d+1] * inv, acc[d+2] * inv, acc[d+3] * inv);
        *(float4*)&op[d] = vv;
    }
}

// ---------------------------------------------------------------------------
// Launch: 3 projections -> attention -> output projection
// ---------------------------------------------------------------------------
extern "C" void kernel_launch(void* const* d_in, const int* in_sizes, int n_in,
                              void* d_out, int out_size)
{
    const float* k  = (const float*)d_in[0];
    const float* v  = (const float*)d_in[1];
    const float* q  = (const float*)d_in[2];
    const float* Wk = (const float*)d_in[3];
    const float* Wv = (const float*)d_in[4];
    const float* Wq = (const float*)d_in[5];
    const float* Wo = (const float*)d_in[6];
    float* out = (float*)d_out;

    dim3 gridG(Ec / 128, Mtot / 128);   // (8, 64)
    gemm_kernel<0><<<gridG, 256>>>(k, Wk, nullptr);
    gemm_kernel<1><<<gridG, 256>>>(v, Wv, nullptr);
    gemm_kernel<2><<<gridG, 256>>>(q, Wq, nullptr);

    attn_kernel<<<dim3(Sc / 128, Hc, Bc), 128>>>();

    gemm_kernel<3><<<gridG, 256>>>(nullptr, Wo, out);
}

// round 3
// speedup vs baseline: 1.2512x; 1.2512x over previous
#include <cuda_runtime.h>
#include <math.h>
#include <stdint.h>

// Problem constants
#define Bc 4
#define Sc 2048
#define Ec 1024
#define Hc 16
#define Dc 64
#define Mtot (Bc*Sc)   // 8192
#define Kdim 1024

// GEMM tiling
#define MT 128
#define NT 128
#define KT 16
#define KTILES (Kdim/KT)   // 64
#define PAD 20             // smem row stride in floats (conflict-free for mma frag pattern)

// Scratch (allocation-free: __device__ globals)
__device__ float g_kp[Bc*Hc*Sc*Dc];   // [B,H,S,D] fp32
__device__ float g_vp[Bc*Hc*Sc*Dc];
__device__ float g_qp[Bc*Hc*Sc*Dc];   // pre-scaled by 1/8
__device__ float g_ctx[Bc*Sc*Ec];     // [B,S,E], tf32-rounded by attn epilogue
__device__ float g_rA[Mtot*Ec];       // tf32-rounded activation (reused for k,v,q)
__device__ float g_rW[4*Ec*Ec];       // tf32-rounded weights

// ---------------------------------------------------------------------------
// helpers
// ---------------------------------------------------------------------------
__device__ __forceinline__ uint32_t smem_u32(const void* p) {
    uint32_t a;
    asm("{ .reg .u64 t; cvta.to.shared.u64 t, %1; cvt.u32.u64 %0, t; }" : "=r"(a) : "l"(p));
    return a;
}
__device__ __forceinline__ float rna_tf32(float x) {
    uint32_t u;
    asm("cvt.rna.tf32.f32 %0, %1;" : "=r"(u) : "f"(x));
    return __uint_as_float(u);
}
#define CP_ASYNC16(dst, src) \
    asm volatile("cp.async.cg.shared.global [%0], [%1], 16;" :: "r"(dst), "l"(src))
#define CP_COMMIT() asm volatile("cp.async.commit_group;" ::: "memory")
#define CP_WAIT(n)  asm volatile("cp.async.wait_group %0;" :: "n"(n) : "memory")

#define MMA_TF32(d, a, b) \
    asm volatile("mma.sync.aligned.m16n8k8.row.col.f32.tf32.tf32.f32 " \
        "{%0,%1,%2,%3}, {%4,%5,%6,%7}, {%8,%9}, {%0,%1,%2,%3};" \
        : "+f"((d)[0]), "+f"((d)[1]), "+f"((d)[2]), "+f"((d)[3]) \
        : "r"((a)[0]), "r"((a)[1]), "r"((a)[2]), "r"((a)[3]), \
          "r"((b)[0]), "r"((b)[1]))

// ---------------------------------------------------------------------------
// tf32-RNE rounding pre-pass
// ---------------------------------------------------------------------------
__global__ __launch_bounds__(256) void round_tf32_kernel(const float4* __restrict__ in,
                                                         float4* __restrict__ out, int n4) {
    int i = blockIdx.x * blockDim.x + threadIdx.x;
    if (i >= n4) return;
    float4 v = in[i];
    v.x = rna_tf32(v.x); v.y = rna_tf32(v.y); v.z = rna_tf32(v.z); v.w = rna_tf32(v.w);
    out[i] = v;
}

// ---------------------------------------------------------------------------
// tf32 mma.sync GEMM: C[M,N] = A[M,K] @ W[N,K]^T   (M=8192, N=K=1024)
// 128x128 tile, KT=16 double-buffered cp.async, 8 warps, warp tile 64x32.
// LAYOUT 0: scatter into [B,H,S,D] with scale; LAYOUT 1: plain [M,N]
// ---------------------------------------------------------------------------
template <int LAYOUT>
__global__ __launch_bounds__(256, 2) void gemm_tc(const float* __restrict__ A,
                                                  const float* __restrict__ W,
                                                  float* __restrict__ Cout, float scale)
{
    __shared__ float As[2][MT][PAD];
    __shared__ float Bs[2][NT][PAD];

    const int tid  = threadIdx.x;
    const int wid  = tid >> 5;
    const int lane = tid & 31;
    const int warp_m = wid & 1;       // 0..1 (64 rows each)
    const int warp_n = wid >> 1;      // 0..3 (32 cols each)

    const int n0 = blockIdx.x * NT;
    const int m0 = blockIdx.y * MT;

    // stage loader: 512 16B-chunks per matrix, 2 per thread
    auto load_tile = [&](int kt, int buf) {
        const int k0 = kt * KT;
        #pragma unroll
        for (int i = 0; i < 2; i++) {
            int c = tid + i * 256;
            int row = c >> 2, seg = c & 3;
            CP_ASYNC16(smem_u32(&As[buf][row][seg * 4]),
                       A + (size_t)(m0 + row) * Kdim + k0 + seg * 4);
            CP_ASYNC16(smem_u32(&Bs[buf][row][seg * 4]),
                       W + (size_t)(n0 + row) * Kdim + k0 + seg * 4);
        }
    };

    float acc[4][4][4];
    #pragma unroll
    for (int i = 0; i < 4; i++)
        #pragma unroll
        for (int j = 0; j < 4; j++)
            #pragma unroll
            for (int r = 0; r < 4; r++) acc[i][j][r] = 0.0f;

    load_tile(0, 0);
    CP_COMMIT();

    const int fr = lane >> 2;   // 0..7
    const int fc = lane & 3;    // 0..3

    for (int kt = 0; kt < KTILES; kt++) {
        const int buf = kt & 1;
        if (kt + 1 < KTILES) {
            load_tile(kt + 1, buf ^ 1);
            CP_COMMIT();
            CP_WAIT(1);
        } else {
            CP_WAIT(0);
        }
        __syncthreads();

        #pragma unroll
        for (int ks = 0; ks < KT; ks += 8) {
            uint32_t af[4][4], bf[4][2];
            #pragma unroll
            for (int mt = 0; mt < 4; mt++) {
                int row = warp_m * 64 + mt * 16 + fr;
                af[mt][0] = __float_as_uint(As[buf][row    ][ks + fc]);
                af[mt][1] = __float_as_uint(As[buf][row + 8][ks + fc]);
                af[mt][2] = __float_as_uint(As[buf][row    ][ks + fc + 4]);
                af[mt][3] = __float_as_uint(As[buf][row + 8][ks + fc + 4]);
            }
            #pragma unroll
            for (int nt = 0; nt < 4; nt++) {
                int col = warp_n * 32 + nt * 8 + fr;
                if (fr < 8) {
                    bf[nt][0] = __float_as_uint(Bs[buf][col][ks + fc]);
                    bf[nt][1] = __float_as_uint(Bs[buf][col][ks + fc + 4]);
                }
            }
            #pragma unroll
            for (int mt = 0; mt < 4; mt++)
                #pragma unroll
                for (int nt = 0; nt < 4; nt++)
                    MMA_TF32(acc[mt][nt], af[mt], bf[nt]);
        }
        __syncthreads();
    }

    // Epilogue: c-frag: rows fr, fr+8 ; cols fc*2, fc*2+1 (contiguous pair)
    #pragma unroll
    for (int mt = 0; mt < 4; mt++) {
        #pragma unroll
        for (int nt = 0; nt < 4; nt++) {
            int n = n0 + warp_n * 32 + nt * 8 + fc * 2;
            #pragma unroll
            for (int half = 0; half < 2; half++) {
                int m = m0 + warp_m * 64 + mt * 16 + fr + half * 8;
                float2 vv = make_float2(acc[mt][nt][half * 2] * scale,
                                        acc[mt][nt][half * 2 + 1] * scale);
                if (LAYOUT == 1) {
                    *(float2*)&Cout[(size_t)m * Ec + n] = vv;
                } else {
                    int b = m >> 11, s = m & 2047;
                    int h = n >> 6,  d = n & 63;
                    *(float2*)&Cout[(size_t)(((b * Hc + h) * Sc) + s) * Dc + d] = vv;
                }
            }
        }
    }
}

// ---------------------------------------------------------------------------
// Flash attention (causal), fp32. 2 threads per query (32 D-dims each),
// 128 queries/block, 32-key tiles, 16-key score sub-tiles. Online softmax.
// ---------------------------------------------------------------------------
__global__ __launch_bounds__(256, 2) void attn_kernel()
{
    const int b  = blockIdx.z;
    const int h  = blockIdx.y;
    const int qb = (gridDim.x - 1) - blockIdx.x;   // heavy tiles first
    const int tid = threadIdx.x;
    const int ql = tid >> 1;
    const int hf = tid & 1;
    const int qidx = qb * 128 + ql;

    __shared__ float Ks[32][64];
    __shared__ float Vs[32][64];

    const size_t bh = (size_t)(b * Hc + h) * Sc;
    const float* qbase = g_qp + (bh + qidx) * Dc + hf * 32;
    const float* kbase = g_kp + bh * Dc;
    const float* vbase = g_vp + bh * Dc;

    float qreg[32];
    #pragma unroll
    for (int d = 0; d < 32; d += 4) {
        float4 v = *(const float4*)&qbase[d];
        qreg[d] = v.x; qreg[d+1] = v.y; qreg[d+2] = v.z; qreg[d+3] = v.w;
    }

    float acc[32];
    #pragma unroll
    for (int d = 0; d < 32; d++) acc[d] = 0.0f;
    float mmax = -INFINITY;
    float lsum = 0.0f;

    const int nk = qb * 128 + 128;

    for (int k0 = 0; k0 < nk; k0 += 32) {
        __syncthreads();
        const float4* ksrc = (const float4*)(kbase + (size_t)k0 * 64);
        const float4* vsrc = (const float4*)(vbase + (size_t)k0 * 64);
        ((float4*)Ks)[tid]       = ksrc[tid];
        ((float4*)Ks)[tid + 256] = ksrc[tid + 256];
        ((float4*)Vs)[tid]       = vsrc[tid];
        ((float4*)Vs)[tid + 256] = vsrc[tid + 256];
        __syncthreads();

        #pragma unroll
        for (int sub = 0; sub < 2; sub++) {
            float sc[16];
            #pragma unroll
            for (int j = 0; j < 16; j++) {
                const int kj = sub * 16 + j;
                float s = 0.0f;
                const float* kr = &Ks[kj][hf * 32];
                #pragma unroll
                for (int d = 0; d < 32; d += 4) {
                    float4 kv = *(const float4*)&kr[d];
                    s = fmaf(qreg[d],   kv.x, s);
                    s = fmaf(qreg[d+1], kv.y, s);
                    s = fmaf(qreg[d+2], kv.z, s);
                    s = fmaf(qreg[d+3], kv.w, s);
                }
                s += __shfl_xor_sync(0xffffffffu, s, 1);
                sc[j] = (k0 + kj <= qidx) ? s : -1e30f;
            }
            float tmax = sc[0];
            #pragma unroll
            for (int j = 1; j < 16; j++) tmax = fmaxf(tmax, sc[j]);
            float mnew = fmaxf(mmax, tmax);
            float corr = __expf(mmax - mnew);
            lsum *= corr;
            #pragma unroll
            for (int d = 0; d < 32; d++) acc[d] *= corr;

            #pragma unroll
            for (int j = 0; j < 16; j++) {
                const int kj = sub * 16 + j;
                float p = __expf(sc[j] - mnew);
                lsum += p;
                const float* vr = &Vs[kj][hf * 32];
                #pragma unroll
                for (int d = 0; d < 32; d += 4) {
                    float4 vv = *(const float4*)&vr[d];
                    acc[d]   = fmaf(p, vv.x, acc[d]);
                    acc[d+1] = fmaf(p, vv.y, acc[d+1]);
                    acc[d+2] = fmaf(p, vv.z, acc[d+2]);
                    acc[d+3] = fmaf(p, vv.w, acc[d+3]);
                }
            }
            mmax = mnew;
        }
    }

    const float inv = 1.0f / lsum;
    float* op = g_ctx + ((size_t)b * Sc + qidx) * Ec + h * Dc + hf * 32;
    #pragma unroll
    for (int d = 0; d < 32; d += 4) {
        float4 vv = make_float4(rna_tf32(acc[d]   * inv), rna_tf32(acc[d+1] * inv),
                                rna_tf32(acc[d+2] * inv), rna_tf32(acc[d+3] * inv));
        *(float4*)&op[d] = vv;
    }
}

// ---------------------------------------------------------------------------
// Launch
// ---------------------------------------------------------------------------
extern "C" void kernel_launch(void* const* d_in, const int* in_sizes, int n_in,
                              void* d_out, int out_size)
{
    const float* k  = (const float*)d_in[0];
    const float* v  = (const float*)d_in[1];
    const float* q  = (const float*)d_in[2];
    const float* Wk = (const float*)d_in[3];
    const float* Wv = (const float*)d_in[4];
    const float* Wq = (const float*)d_in[5];
    const float* Wo = (const float*)d_in[6];
    float* out = (float*)d_out;

    float* rA = nullptr; cudaGetSymbolAddress((void**)&rA, g_rA);
    float* rW = nullptr; cudaGetSymbolAddress((void**)&rW, g_rW);
    float* kp = nullptr; cudaGetSymbolAddress((void**)&kp, g_kp);
    float* vp = nullptr; cudaGetSymbolAddress((void**)&vp, g_vp);
    float* qp = nullptr; cudaGetSymbolAddress((void**)&qp, g_qp);
    float* ctx = nullptr; cudaGetSymbolAddress((void**)&ctx, g_ctx);

    const int nW4 = Ec * Ec / 4;      // 262144
    const int nA4 = Mtot * Ec / 4;    // 2097152

    // round weights to tf32-RNE
    round_tf32_kernel<<<nW4 / 256, 256>>>((const float4*)Wk, (float4*)(rW + 0 * Ec * Ec), nW4);
    round_tf32_kernel<<<nW4 / 256, 256>>>((const float4*)Wv, (float4*)(rW + 1 * Ec * Ec), nW4);
    round_tf32_kernel<<<nW4 / 256, 256>>>((const float4*)Wq, (float4*)(rW + 2 * Ec * Ec), nW4);
    round_tf32_kernel<<<nW4 / 256, 256>>>((const float4*)Wo, (float4*)(rW + 3 * Ec * Ec), nW4);

    dim3 gridG(Ec / NT, Mtot / MT);   // (8, 64)

    round_tf32_kernel<<<nA4 / 256, 256>>>((const float4*)k, (float4*)rA, nA4);
    gemm_tc<0><<<gridG, 256>>>(rA, rW + 0 * Ec * Ec, kp, 1.0f);

    round_tf32_kernel<<<nA4 / 256, 256>>>((const float4*)v, (float4*)rA, nA4);
    gemm_tc<0><<<gridG, 256>>>(rA, rW + 1 * Ec * Ec, vp, 1.0f);

    round_tf32_kernel<<<nA4 / 256, 256>>>((const float4*)q, (float4*)rA, nA4);
    gemm_tc<0><<<gridG, 256>>>(rA, rW + 2 * Ec * Ec, qp, 0.125f);

    attn_kernel<<<dim3(Sc / 128, Hc, Bc), 256>>>();

    gemm_tc<1><<<gridG, 256>>>(ctx, rW + 3 * Ec * Ec, out, 1.0f);
}

// round 4
// speedup vs baseline: 1.2643x; 1.0105x over previous
#include <cuda_runtime.h>
#include <math.h>
#include <stdint.h>

// Problem constants
#define Bc 4
#define Sc 2048
#define Ec 1024
#define Hc 16
#define Dc 64
#define Mtot (Bc*Sc)   // 8192
#define Kdim 1024

// GEMM tiling
#define MT 128
#define NT 128
#define KT 16
#define KTILES (Kdim/KT)   // 64
#define PAD 20             // smem row stride in floats (conflict-free for mma frag pattern)

// Scratch (allocation-free: __device__ globals)
__device__ float g_kp[Bc*Hc*Sc*Dc];   // [B,H,S,D] fp32
__device__ float g_vp[Bc*Hc*Sc*Dc];
__device__ float g_qp[Bc*Hc*Sc*Dc];   // pre-scaled by 1/8
__device__ float g_ctx[Bc*Sc*Ec];     // [B,S,E], tf32-rounded by attn epilogue
__device__ float g_rA[Mtot*Ec];       // tf32-rounded activation (reused for k,v,q)
__device__ float g_rW[4*Ec*Ec];       // tf32-rounded weights

// ---------------------------------------------------------------------------
// helpers
// ---------------------------------------------------------------------------
__device__ __forceinline__ uint32_t smem_u32(const void* p) {
    uint32_t a;
    asm("{ .reg .u64 t; cvta.to.shared.u64 t, %1; cvt.u32.u64 %0, t; }" : "=r"(a) : "l"(p));
    return a;
}
__device__ __forceinline__ float rna_tf32(float x) {
    uint32_t u;
    asm("cvt.rna.tf32.f32 %0, %1;" : "=r"(u) : "f"(x));
    return __uint_as_float(u);
}
#define CP_ASYNC16(dst, src) \
    asm volatile("cp.async.cg.shared.global [%0], [%1], 16;" :: "r"(dst), "l"(src))
#define CP_COMMIT() asm volatile("cp.async.commit_group;" ::: "memory")
#define CP_WAIT(n)  asm volatile("cp.async.wait_group %0;" :: "n"(n) : "memory")

#define MMA_TF32(d, a, b) \
    asm volatile("mma.sync.aligned.m16n8k8.row.col.f32.tf32.tf32.f32 " \
        "{%0,%1,%2,%3}, {%4,%5,%6,%7}, {%8,%9}, {%0,%1,%2,%3};" \
        : "+f"((d)[0]), "+f"((d)[1]), "+f"((d)[2]), "+f"((d)[3]) \
        : "r"((a)[0]), "r"((a)[1]), "r"((a)[2]), "r"((a)[3]), \
          "r"((b)[0]), "r"((b)[1]))

// ---------------------------------------------------------------------------
// tf32-RNE rounding pre-pass
// ---------------------------------------------------------------------------
__global__ __launch_bounds__(256) void round_tf32_kernel(const float4* __restrict__ in,
                                                         float4* __restrict__ out, int n4) {
    int i = blockIdx.x * blockDim.x + threadIdx.x;
    if (i >= n4) return;
    float4 v = in[i];
    v.x = rna_tf32(v.x); v.y = rna_tf32(v.y); v.z = rna_tf32(v.z); v.w = rna_tf32(v.w);
    out[i] = v;
}

// ---------------------------------------------------------------------------
// tf32 mma.sync GEMM: C[M,N] = A[M,K] @ W[N,K]^T   (M=8192, N=K=1024)
// 128x128 tile, KT=16 double-buffered cp.async, 8 warps, warp tile 64x32.
// LAYOUT 0: scatter into [B,H,S,D] with scale; LAYOUT 1: plain [M,N]
// ---------------------------------------------------------------------------
template <int LAYOUT>
__global__ __launch_bounds__(256, 2) void gemm_tc(const float* __restrict__ A,
                                                  const float* __restrict__ W,
                                                  float* __restrict__ Cout, float scale)
{
    __shared__ float As[2][MT][PAD];
    __shared__ float Bs[2][NT][PAD];

    const int tid  = threadIdx.x;
    const int wid  = tid >> 5;
    const int lane = tid & 31;
    const int warp_m = wid & 1;       // 0..1 (64 rows each)
    const int warp_n = wid >> 1;      // 0..3 (32 cols each)

    const int n0 = blockIdx.x * NT;
    const int m0 = blockIdx.y * MT;

    // stage loader: 512 16B-chunks per matrix, 2 per thread
    auto load_tile = [&](int kt, int buf) {
        const int k0 = kt * KT;
        #pragma unroll
        for (int i = 0; i < 2; i++) {
            int c = tid + i * 256;
            int row = c >> 2, seg = c & 3;
            CP_ASYNC16(smem_u32(&As[buf][row][seg * 4]),
                       A + (size_t)(m0 + row) * Kdim + k0 + seg * 4);
            CP_ASYNC16(smem_u32(&Bs[buf][row][seg * 4]),
                       W + (size_t)(n0 + row) * Kdim + k0 + seg * 4);
        }
    };

    float acc[4][4][4];
    #pragma unroll
    for (int i = 0; i < 4; i++)
        #pragma unroll
        for (int j = 0; j < 4; j++)
            #pragma unroll
            for (int r = 0; r < 4; r++) acc[i][j][r] = 0.0f;

    load_tile(0, 0);
    CP_COMMIT();

    const int fr = lane >> 2;   // 0..7
    const int fc = lane & 3;    // 0..3

    for (int kt = 0; kt < KTILES; kt++) {
        const int buf = kt & 1;
        if (kt + 1 < KTILES) {
            load_tile(kt + 1, buf ^ 1);
            CP_COMMIT();
            CP_WAIT(1);
        } else {
            CP_WAIT(0);
        }
        __syncthreads();

        #pragma unroll
        for (int ks = 0; ks < KT; ks += 8) {
            uint32_t af[4][4], bf[4][2];
            #pragma unroll
            for (int mt = 0; mt < 4; mt++) {
                int row = warp_m * 64 + mt * 16 + fr;
                af[mt][0] = __float_as_uint(As[buf][row    ][ks + fc]);
                af[mt][1] = __float_as_uint(As[buf][row + 8][ks + fc]);
                af[mt][2] = __float_as_uint(As[buf][row    ][ks + fc + 4]);
                af[mt][3] = __float_as_uint(As[buf][row + 8][ks + fc + 4]);
            }
            #pragma unroll
            for (int nt = 0; nt < 4; nt++) {
                int col = warp_n * 32 + nt * 8 + fr;
                if (fr < 8) {
                    bf[nt][0] = __float_as_uint(Bs[buf][col][ks + fc]);
                    bf[nt][1] = __float_as_uint(Bs[buf][col][ks + fc + 4]);
                }
            }
            #pragma unroll
            for (int mt = 0; mt < 4; mt++)
                #pragma unroll
                for (int nt = 0; nt < 4; nt++)
                    MMA_TF32(acc[mt][nt], af[mt], bf[nt]);
        }
        __syncthreads();
    }

    // Epilogue: c-frag: rows fr, fr+8 ; cols fc*2, fc*2+1 (contiguous pair)
    #pragma unroll
    for (int mt = 0; mt < 4; mt++) {
        #pragma unroll
        for (int nt = 0; nt < 4; nt++) {
            int n = n0 + warp_n * 32 + nt * 8 + fc * 2;
            #pragma unroll
            for (int half = 0; half < 2; half++) {
                int m = m0 + warp_m * 64 + mt * 16 + fr + half * 8;
                float2 vv = make_float2(acc[mt][nt][half * 2] * scale,
                                        acc[mt][nt][half * 2 + 1] * scale);
                if (LAYOUT == 1) {
                    *(float2*)&Cout[(size_t)m * Ec + n] = vv;
                } else {
                    int b = m >> 11, s = m & 2047;
                    int h = n >> 6,  d = n & 63;
                    *(float2*)&Cout[(size_t)(((b * Hc + h) * Sc) + s) * Dc + d] = vv;
                }
            }
        }
    }
}

// ---------------------------------------------------------------------------
// Flash attention (causal), fp32. 2 threads per query (32 D-dims each),
// 128 queries/block, 32-key tiles, 16-key score sub-tiles. Online softmax.
// ---------------------------------------------------------------------------
__global__ __launch_bounds__(256, 2) void attn_kernel()
{
    const int b  = blockIdx.z;
    const int h  = blockIdx.y;
    const int qb = (gridDim.x - 1) - blockIdx.x;   // heavy tiles first
    const int tid = threadIdx.x;
    const int ql = tid >> 1;
    const int hf = tid & 1;
    const int qidx = qb * 128 + ql;

    __shared__ float Ks[32][64];
    __shared__ float Vs[32][64];

    const size_t bh = (size_t)(b * Hc + h) * Sc;
    const float* qbase = g_qp + (bh + qidx) * Dc + hf * 32;
    const float* kbase = g_kp + bh * Dc;
    const float* vbase = g_vp + bh * Dc;

    float qreg[32];
    #pragma unroll
    for (int d = 0; d < 32; d += 4) {
        float4 v = *(const float4*)&qbase[d];
        qreg[d] = v.x; qreg[d+1] = v.y; qreg[d+2] = v.z; qreg[d+3] = v.w;
    }

    float acc[32];
    #pragma unroll
    for (int d = 0; d < 32; d++) acc[d] = 0.0f;
    float mmax = -INFINITY;
    float lsum = 0.0f;

    const int nk = qb * 128 + 128;

    for (int k0 = 0; k0 < nk; k0 += 32) {
        __syncthreads();
        const float4* ksrc = (const float4*)(kbase + (size_t)k0 * 64);
        const float4* vsrc = (const float4*)(vbase + (size_t)k0 * 64);
        ((float4*)Ks)[tid]       = ksrc[tid];
        ((float4*)Ks)[tid + 256] = ksrc[tid + 256];
        ((float4*)Vs)[tid]       = vsrc[tid];
        ((float4*)Vs)[tid + 256] = vsrc[tid + 256];
        __syncthreads();

        #pragma unroll
        for (int sub = 0; sub < 2; sub++) {
            float sc[16];
            #pragma unroll
            for (int j = 0; j < 16; j++) {
                const int kj = sub * 16 + j;
                float s = 0.0f;
                const float* kr = &Ks[kj][hf * 32];
                #pragma unroll
                for (int d = 0; d < 32; d += 4) {
                    float4 kv = *(const float4*)&kr[d];
                    s = fmaf(qreg[d],   kv.x, s);
                    s = fmaf(qreg[d+1], kv.y, s);
                    s = fmaf(qreg[d+2], kv.z, s);
                    s = fmaf(qreg[d+3], kv.w, s);
                }
                s += __shfl_xor_sync(0xffffffffu, s, 1);
                sc[j] = (k0 + kj <= qidx) ? s : -1e30f;
            }
            float tmax = sc[0];
            #pragma unroll
            for (int j = 1; j < 16; j++) tmax = fmaxf(tmax, sc[j]);
            float mnew = fmaxf(mmax, tmax);
            float corr = __expf(mmax - mnew);
            lsum *= corr;
            #pragma unroll
            for (int d = 0; d < 32; d++) acc[d] *= corr;

            #pragma unroll
            for (int j = 0; j < 16; j++) {
                const int kj = sub * 16 + j;
                float p = __expf(sc[j] - mnew);
                lsum += p;
                const float* vr = &Vs[kj][hf * 32];
                #pragma unroll
                for (int d = 0; d < 32; d += 4) {
                    float4 vv = *(const float4*)&vr[d];
                    acc[d]   = fmaf(p, vv.x, acc[d]);
                    acc[d+1] = fmaf(p, vv.y, acc[d+1]);
                    acc[d+2] = fmaf(p, vv.z, acc[d+2]);
                    acc[d+3] = fmaf(p, vv.w, acc[d+3]);
                }
            }
            mmax = mnew;
        }
    }

    const float inv = 1.0f / lsum;
    float* op = g_ctx + ((size_t)b * Sc + qidx) * Ec + h * Dc + hf * 32;
    #pragma unroll
    for (int d = 0; d < 32; d += 4) {
        float4 vv = make_float4(rna_tf32(acc[d]   * inv), rna_tf32(acc[d+1] * inv),
                                rna_tf32(acc[d+2] * inv), rna_tf32(acc[d+3] * inv));
        *(float4*)&op[d] = vv;
    }
}

// ---------------------------------------------------------------------------
// Launch
// ---------------------------------------------------------------------------
extern "C" void kernel_launch(void* const* d_in, const int* in_sizes, int n_in,
                              void* d_out, int out_size)
{
    const float* k  = (const float*)d_in[0];
    const float* v  = (const float*)d_in[1];
    const float* q  = (const float*)d_in[2];
    const float* Wk = (const float*)d_in[3];
    const float* Wv = (const float*)d_in[4];
    const float* Wq = (const float*)d_in[5];
    const float* Wo = (const float*)d_in[6];
    float* out = (float*)d_out;

    float* rA = nullptr; cudaGetSymbolAddress((void**)&rA, g_rA);
    float* rW = nullptr; cudaGetSymbolAddress((void**)&rW, g_rW);
    float* kp = nullptr; cudaGetSymbolAddress((void**)&kp, g_kp);
    float* vp = nullptr; cudaGetSymbolAddress((void**)&vp, g_vp);
    float* qp = nullptr; cudaGetSymbolAddress((void**)&qp, g_qp);
    float* ctx = nullptr; cudaGetSymbolAddress((void**)&ctx, g_ctx);

    const int nW4 = Ec * Ec / 4;      // 262144
    const int nA4 = Mtot * Ec / 4;    // 2097152

    // round weights to tf32-RNE
    round_tf32_kernel<<<nW4 / 256, 256>>>((const float4*)Wk, (float4*)(rW + 0 * Ec * Ec), nW4);
    round_tf32_kernel<<<nW4 / 256, 256>>>((const float4*)Wv, (float4*)(rW + 1 * Ec * Ec), nW4);
    round_tf32_kernel<<<nW4 / 256, 256>>>((const float4*)Wq, (float4*)(rW + 2 * Ec * Ec), nW4);
    round_tf32_kernel<<<nW4 / 256, 256>>>((const float4*)Wo, (float4*)(rW + 3 * Ec * Ec), nW4);

    dim3 gridG(Ec / NT, Mtot / MT);   // (8, 64)

    round_tf32_kernel<<<nA4 / 256, 256>>>((const float4*)k, (float4*)rA, nA4);
    gemm_tc<0><<<gridG, 256>>>(rA, rW + 0 * Ec * Ec, kp, 1.0f);

    round_tf32_kernel<<<nA4 / 256, 256>>>((const float4*)v, (float4*)rA, nA4);
    gemm_tc<0><<<gridG, 256>>>(rA, rW + 1 * Ec * Ec, vp, 1.0f);

    round_tf32_kernel<<<nA4 / 256, 256>>>((const float4*)q, (float4*)rA, nA4);
    gemm_tc<0><<<gridG, 256>>>(rA, rW + 2 * Ec * Ec, qp, 0.125f);

    attn_kernel<<<dim3(Sc / 128, Hc, Bc), 256>>>();

    gemm_tc<1><<<gridG, 256>>>(ctx, rW + 3 * Ec * Ec, out, 1.0f);
}

// round 5
// speedup vs baseline: 3.9206x; 3.1010x over previous
#include <cuda_runtime.h>
#include <math.h>
#include <stdint.h>

// Problem constants
#define Bc 4
#define Sc 2048
#define Ec 1024
#define Hc 16
#define Dc 64
#define Mtot (Bc*Sc)   // 8192
#define Kdim 1024

// GEMM tiling
#define MT 128
#define NT 128
#define KT 16
#define KTILES (Kdim/KT)   // 64
#define PAD 20

// Scratch (allocation-free: __device__ globals)
__device__ float g_kp[Bc*Hc*Sc*Dc];   // [B,H,S,D] tf32-rounded
__device__ float g_vp[Bc*Hc*Sc*Dc];   // tf32-rounded
__device__ float g_qp[Bc*Hc*Sc*Dc];   // pre-scaled by 1/8, tf32-rounded
__device__ float g_ctx[Bc*Sc*Ec];     // [B,S,E], tf32-rounded
__device__ float g_rA[Mtot*Ec];
__device__ float g_rW[4*Ec*Ec];

// ---------------------------------------------------------------------------
// helpers
// ---------------------------------------------------------------------------
__device__ __forceinline__ uint32_t smem_u32(const void* p) {
    uint32_t a;
    asm("{ .reg .u64 t; cvta.to.shared.u64 t, %1; cvt.u32.u64 %0, t; }" : "=r"(a) : "l"(p));
    return a;
}
__device__ __forceinline__ float rna_tf32(float x) {
    uint32_t u;
    asm("cvt.rna.tf32.f32 %0, %1;" : "=r"(u) : "f"(x));
    return __uint_as_float(u);
}
#define CP_ASYNC16(dst, src) \
    asm volatile("cp.async.cg.shared.global [%0], [%1], 16;" :: "r"(dst), "l"(src))
#define CP_COMMIT() asm volatile("cp.async.commit_group;" ::: "memory")
#define CP_WAIT(n)  asm volatile("cp.async.wait_group %0;" :: "n"(n) : "memory")

#define MMA_TF32(d, a, b) \
    asm volatile("mma.sync.aligned.m16n8k8.row.col.f32.tf32.tf32.f32 " \
        "{%0,%1,%2,%3}, {%4,%5,%6,%7}, {%8,%9}, {%0,%1,%2,%3};" \
        : "+f"((d)[0]), "+f"((d)[1]), "+f"((d)[2]), "+f"((d)[3]) \
        : "r"((a)[0]), "r"((a)[1]), "r"((a)[2]), "r"((a)[3]), \
          "r"((b)[0]), "r"((b)[1]))

// ---------------------------------------------------------------------------
// tf32-RNE rounding pre-pass
// ---------------------------------------------------------------------------
__global__ __launch_bounds__(256) void round_tf32_kernel(const float4* __restrict__ in,
                                                         float4* __restrict__ out, int n4) {
    int i = blockIdx.x * blockDim.x + threadIdx.x;
    if (i >= n4) return;
    float4 v = in[i];
    v.x = rna_tf32(v.x); v.y = rna_tf32(v.y); v.z = rna_tf32(v.z); v.w = rna_tf32(v.w);
    out[i] = v;
}

// ---------------------------------------------------------------------------
// tf32 mma.sync GEMM: C[M,N] = A[M,K] @ W[N,K]^T   (M=8192, N=K=1024)
// LAYOUT 0: scatter into [B,H,S,D] with scale + tf32-round; LAYOUT 1: plain [M,N]
// ---------------------------------------------------------------------------
template <int LAYOUT>
__global__ __launch_bounds__(256, 2) void gemm_tc(const float* __restrict__ A,
                                                  const float* __restrict__ W,
                                                  float* __restrict__ Cout, float scale)
{
    __shared__ float As[2][MT][PAD];
    __shared__ float Bs[2][NT][PAD];

    const int tid  = threadIdx.x;
    const int wid  = tid >> 5;
    const int lane = tid & 31;
    const int warp_m = wid & 1;
    const int warp_n = wid >> 1;

    const int n0 = blockIdx.x * NT;
    const int m0 = blockIdx.y * MT;

    auto load_tile = [&](int kt, int buf) {
        const int k0 = kt * KT;
        #pragma unroll
        for (int i = 0; i < 2; i++) {
            int c = tid + i * 256;
            int row = c >> 2, seg = c & 3;
            CP_ASYNC16(smem_u32(&As[buf][row][seg * 4]),
                       A + (size_t)(m0 + row) * Kdim + k0 + seg * 4);
            CP_ASYNC16(smem_u32(&Bs[buf][row][seg * 4]),
                       W + (size_t)(n0 + row) * Kdim + k0 + seg * 4);
        }
    };

    float acc[4][4][4];
    #pragma unroll
    for (int i = 0; i < 4; i++)
        #pragma unroll
        for (int j = 0; j < 4; j++)
            #pragma unroll
            for (int r = 0; r < 4; r++) acc[i][j][r] = 0.0f;

    load_tile(0, 0);
    CP_COMMIT();

    const int fr = lane >> 2;
    const int fc = lane & 3;

    for (int kt = 0; kt < KTILES; kt++) {
        const int buf = kt & 1;
        if (kt + 1 < KTILES) {
            load_tile(kt + 1, buf ^ 1);
            CP_COMMIT();
            CP_WAIT(1);
        } else {
            CP_WAIT(0);
        }
        __syncthreads();

        #pragma unroll
        for (int ks = 0; ks < KT; ks += 8) {
            uint32_t af[4][4], bf[4][2];
            #pragma unroll
            for (int mt = 0; mt < 4; mt++) {
                int row = warp_m * 64 + mt * 16 + fr;
                af[mt][0] = __float_as_uint(As[buf][row    ][ks + fc]);
                af[mt][1] = __float_as_uint(As[buf][row + 8][ks + fc]);
                af[mt][2] = __float_as_uint(As[buf][row    ][ks + fc + 4]);
                af[mt][3] = __float_as_uint(As[buf][row + 8][ks + fc + 4]);
            }
            #pragma unroll
            for (int nt = 0; nt < 4; nt++) {
                int col = warp_n * 32 + nt * 8 + fr;
                bf[nt][0] = __float_as_uint(Bs[buf][col][ks + fc]);
                bf[nt][1] = __float_as_uint(Bs[buf][col][ks + fc + 4]);
            }
            #pragma unroll
            for (int mt = 0; mt < 4; mt++)
                #pragma unroll
                for (int nt = 0; nt < 4; nt++)
                    MMA_TF32(acc[mt][nt], af[mt], bf[nt]);
        }
        __syncthreads();
    }

    #pragma unroll
    for (int mt = 0; mt < 4; mt++) {
        #pragma unroll
        for (int nt = 0; nt < 4; nt++) {
            int n = n0 + warp_n * 32 + nt * 8 + fc * 2;
            #pragma unroll
            for (int half = 0; half < 2; half++) {
                int m = m0 + warp_m * 64 + mt * 16 + fr + half * 8;
                if (LAYOUT == 1) {
                    float2 vv = make_float2(acc[mt][nt][half * 2],
                                            acc[mt][nt][half * 2 + 1]);
                    *(float2*)&Cout[(size_t)m * Ec + n] = vv;
                } else {
                    float2 vv = make_float2(rna_tf32(acc[mt][nt][half * 2] * scale),
                                            rna_tf32(acc[mt][nt][half * 2 + 1] * scale));
                    int b = m >> 11, s = m & 2047;
                    int h = n >> 6,  d = n & 63;
                    *(float2*)&Cout[(size_t)(((b * Hc + h) * Sc) + s) * Dc + d] = vv;
                }
            }
        }
    }
}

// ---------------------------------------------------------------------------
// Tensor-core flash attention (causal), tf32 mma.sync.
// Block: 128 queries x (b,h); 8 warps (m16 each). Key tiles of 64.
// smem (floats): Ks 2x[64][68] @0 ; Vs 2x[64][72] @8704 ; P/Q 8x[16][68] @17920
// ---------------------------------------------------------------------------
#define ATTN_SMEM_BYTES ((8704 + 9216 + 8704) * 4)   // 106496

__global__ __launch_bounds__(256) void attn_tc_kernel()
{
    extern __shared__ float sm[];
    const int tid  = threadIdx.x;
    const int wq   = tid >> 5;
    const int lane = tid & 31;
    const int fr   = lane >> 2;
    const int fc   = lane & 3;
    const int b    = blockIdx.z;
    const int h    = blockIdx.y;
    const int qb   = (int)(gridDim.x - 1 - blockIdx.x);   // heavy tiles first

    const size_t bh = (size_t)(b * Hc + h) * Sc;
    const float* kg = g_kp + bh * Dc;
    const float* vg = g_vp + bh * Dc;

    float* Ks = sm;                         // [2][64][68]
    float* Vs = sm + 8704;                  // [2][64][72]
    float* Pq = sm + 17920;                 // [128][68] (Q stage / per-warp P)
    float* Pw = Pq + wq * 16 * 68;          // this warp's [16][68]
    const uint32_t smb = smem_u32(sm);

    // ---- stage Q tile (128 x 64) into P region ----
    {
        const float* qg = g_qp + (bh + (size_t)qb * 128) * Dc;
        #pragma unroll
        for (int i = 0; i < 8; i++) {
            int c = tid + i * 256;          // 0..2047
            int row = c >> 4, seg = c & 15;
            CP_ASYNC16(smb + (uint32_t)(17920 + row * 68 + seg * 4) * 4,
                       qg + (size_t)row * 64 + seg * 4);
        }
        CP_COMMIT(); CP_WAIT(0);
    }
    __syncthreads();

    // Q a-frags for all 8 k-steps (rows wq*16 .. +15 live in this warp's band)
    uint32_t qa[8][4];
    #pragma unroll
    for (int ks = 0; ks < 8; ks++) {
        qa[ks][0] = __float_as_uint(Pw[fr * 68 + ks * 8 + fc]);
        qa[ks][1] = __float_as_uint(Pw[(fr + 8) * 68 + ks * 8 + fc]);
        qa[ks][2] = __float_as_uint(Pw[fr * 68 + ks * 8 + fc + 4]);
        qa[ks][3] = __float_as_uint(Pw[(fr + 8) * 68 + ks * 8 + fc + 4]);
    }

    float o[8][4];
    #pragma unroll
    for (int i = 0; i < 8; i++)
        #pragma unroll
        for (int j = 0; j < 4; j++) o[i][j] = 0.0f;
    float m0 = -INFINITY, m1 = -INFINITY, l0 = 0.0f, l1 = 0.0f;

    const int qrow  = qb * 128 + wq * 16 + fr;   // row0; row1 = qrow+8
    const int qwmin = qb * 128 + wq * 16;
    const int qwmax = qwmin + 15;
    const int cnt   = 2 * qb + 2;

    auto stage_kv = [&](int kt, int buf) {
        const float* kk = kg + (size_t)(kt * 64) * 64;
        const float* vv = vg + (size_t)(kt * 64) * 64;
        #pragma unroll
        for (int i = 0; i < 4; i++) {
            int c = tid + i * 256;          // 0..1023
            int row = c >> 4, seg = c & 15;
            CP_ASYNC16(smb + (uint32_t)(buf * 4352 + row * 68 + seg * 4) * 4,
                       kk + (size_t)row * 64 + seg * 4);
            CP_ASYNC16(smb + (uint32_t)(8704 + buf * 4608 + row * 72 + seg * 4) * 4,
                       vv + (size_t)row * 64 + seg * 4);
        }
    };

    stage_kv(0, 0);
    CP_COMMIT();

    for (int kt = 0; kt < cnt; kt++) {
        const int buf = kt & 1;
        if (kt + 1 < cnt) {
            stage_kv(kt + 1, buf ^ 1);
            CP_COMMIT();
            CP_WAIT(1);
        } else {
            CP_WAIT(0);
        }
        __syncthreads();

        if (kt * 64 <= qwmax) {     // warp has at least one unmasked column
            const float* Kb = Ks + buf * 4352;
            const float* Vb = Vs + buf * 4608;

            // S = Q K^T  (16 x 64 per warp)
            float sc[8][4];
            #pragma unroll
            for (int nt = 0; nt < 8; nt++) {
                sc[nt][0] = sc[nt][1] = sc[nt][2] = sc[nt][3] = 0.0f;
                #pragma unroll
                for (int ks = 0; ks < 8; ks++) {
                    uint32_t bb[2];
                    bb[0] = __float_as_uint(Kb[(nt * 8 + fr) * 68 + ks * 8 + fc]);
                    bb[1] = __float_as_uint(Kb[(nt * 8 + fr) * 68 + ks * 8 + fc + 4]);
                    MMA_TF32(sc[nt], qa[ks], bb);
                }
            }

            // causal mask (only on/above the diagonal band)
            if (kt * 64 + 63 > qwmin) {
                #pragma unroll
                for (int nt = 0; nt < 8; nt++) {
                    int colb = kt * 64 + nt * 8 + 2 * fc;
                    if (colb     > qrow)     sc[nt][0] = -1e30f;
                    if (colb + 1 > qrow)     sc[nt][1] = -1e30f;
                    if (colb     > qrow + 8) sc[nt][2] = -1e30f;
                    if (colb + 1 > qrow + 8) sc[nt][3] = -1e30f;
                }
            }

            // row maxes (local + quad shuffle)
            float t0 = -1e30f, t1 = -1e30f;
            #pragma unroll
            for (int nt = 0; nt < 8; nt++) {
                t0 = fmaxf(t0, fmaxf(sc[nt][0], sc[nt][1]));
                t1 = fmaxf(t1, fmaxf(sc[nt][2], sc[nt][3]));
            }
            t0 = fmaxf(t0, __shfl_xor_sync(0xffffffffu, t0, 1));
            t0 = fmaxf(t0, __shfl_xor_sync(0xffffffffu, t0, 2));
            t1 = fmaxf(t1, __shfl_xor_sync(0xffffffffu, t1, 1));
            t1 = fmaxf(t1, __shfl_xor_sync(0xffffffffu, t1, 2));

            float mn0 = fmaxf(m0, t0), mn1 = fmaxf(m1, t1);
            float c0 = __expf(m0 - mn0), c1 = __expf(m1 - mn1);
            l0 *= c0; l1 *= c1;
            #pragma unroll
            for (int nd = 0; nd < 8; nd++) {
                o[nd][0] *= c0; o[nd][1] *= c0;
                o[nd][2] *= c1; o[nd][3] *= c1;
            }
            m0 = mn0; m1 = mn1;

            // P = exp(S - m), tf32-rounded; stash to per-warp smem
            #pragma unroll
            for (int nt = 0; nt < 8; nt++) {
                float p0 = rna_tf32(__expf(sc[nt][0] - m0));
                float p1 = rna_tf32(__expf(sc[nt][1] - m0));
                float p2 = rna_tf32(__expf(sc[nt][2] - m1));
                float p3 = rna_tf32(__expf(sc[nt][3] - m1));
                l0 += p0 + p1; l1 += p2 + p3;
                *(float2*)&Pw[fr * 68 + nt * 8 + 2 * fc]       = make_float2(p0, p1);
                *(float2*)&Pw[(fr + 8) * 68 + nt * 8 + 2 * fc] = make_float2(p2, p3);
            }
            __syncwarp();

            // O += P V  (16 x 64 per warp)
            #pragma unroll
            for (int ks = 0; ks < 8; ks++) {
                uint32_t pa[4];
                pa[0] = __float_as_uint(Pw[fr * 68 + ks * 8 + fc]);
                pa[1] = __float_as_uint(Pw[(fr + 8) * 68 + ks * 8 + fc]);
                pa[2] = __float_as_uint(Pw[fr * 68 + ks * 8 + fc + 4]);
                pa[3] = __float_as_uint(Pw[(fr + 8) * 68 + ks * 8 + fc + 4]);
                #pragma unroll
                for (int nd = 0; nd < 8; nd++) {
                    uint32_t bb[2];
                    bb[0] = __float_as_uint(Vb[(ks * 8 + fc) * 72 + nd * 8 + fr]);
                    bb[1] = __float_as_uint(Vb[(ks * 8 + fc + 4) * 72 + nd * 8 + fr]);
                    MMA_TF32(o[nd], pa, bb);
                }
            }
        }
        __syncthreads();
    }

    // epilogue: reduce l across quad, normalize, write ctx
    l0 += __shfl_xor_sync(0xffffffffu, l0, 1);
    l0 += __shfl_xor_sync(0xffffffffu, l0, 2);
    l1 += __shfl_xor_sync(0xffffffffu, l1, 1);
    l1 += __shfl_xor_sync(0xffffffffu, l1, 2);
    const float inv0 = 1.0f / l0;
    const float inv1 = 1.0f / l1;

    float* ctx0 = g_ctx + ((size_t)b * Sc + qrow) * Ec + h * Dc;
    float* ctx1 = g_ctx + ((size_t)b * Sc + qrow + 8) * Ec + h * Dc;
    #pragma unroll
    for (int nd = 0; nd < 8; nd++) {
        int col = nd * 8 + 2 * fc;
        *(float2*)&ctx0[col] = make_float2(rna_tf32(o[nd][0] * inv0),
                                           rna_tf32(o[nd][1] * inv0));
        *(float2*)&ctx1[col] = make_float2(rna_tf32(o[nd][2] * inv1),
                                           rna_tf32(o[nd][3] * inv1));
    }
}

// ---------------------------------------------------------------------------
// Launch
// ---------------------------------------------------------------------------
extern "C" void kernel_launch(void* const* d_in, const int* in_sizes, int n_in,
                              void* d_out, int out_size)
{
    const float* k  = (const float*)d_in[0];
    const float* v  = (const float*)d_in[1];
    const float* q  = (const float*)d_in[2];
    const float* Wk = (const float*)d_in[3];
    const float* Wv = (const float*)d_in[4];
    const float* Wq = (const float*)d_in[5];
    const float* Wo = (const float*)d_in[6];
    float* out = (float*)d_out;

    float* rA = nullptr; cudaGetSymbolAddress((void**)&rA, g_rA);
    float* rW = nullptr; cudaGetSymbolAddress((void**)&rW, g_rW);
    float* kp = nullptr; cudaGetSymbolAddress((void**)&kp, g_kp);
    float* vp = nullptr; cudaGetSymbolAddress((void**)&vp, g_vp);
    float* qp = nullptr; cudaGetSymbolAddress((void**)&qp, g_qp);
    float* ctx = nullptr; cudaGetSymbolAddress((void**)&ctx, g_ctx);

    cudaFuncSetAttribute(attn_tc_kernel, cudaFuncAttributeMaxDynamicSharedMemorySize,
                         ATTN_SMEM_BYTES);

    const int nW4 = Ec * Ec / 4;
    const int nA4 = Mtot * Ec / 4;

    round_tf32_kernel<<<nW4 / 256, 256>>>((const float4*)Wk, (float4*)(rW + 0 * Ec * Ec), nW4);
    round_tf32_kernel<<<nW4 / 256, 256>>>((const float4*)Wv, (float4*)(rW + 1 * Ec * Ec), nW4);
    round_tf32_kernel<<<nW4 / 256, 256>>>((const float4*)Wq, (float4*)(rW + 2 * Ec * Ec), nW4);
    round_tf32_kernel<<<nW4 / 256, 256>>>((const float4*)Wo, (float4*)(rW + 3 * Ec * Ec), nW4);

    dim3 gridG(Ec / NT, Mtot / MT);   // (8, 64)

    round_tf32_kernel<<<nA4 / 256, 256>>>((const float4*)k, (float4*)rA, nA4);
    gemm_tc<0><<<gridG, 256>>>(rA, rW + 0 * Ec * Ec, kp, 1.0f);

    round_tf32_kernel<<<nA4 / 256, 256>>>((const float4*)v, (float4*)rA, nA4);
    gemm_tc<0><<<gridG, 256>>>(rA, rW + 1 * Ec * Ec, vp, 1.0f);

    round_tf32_kernel<<<nA4 / 256, 256>>>((const float4*)q, (float4*)rA, nA4);
    gemm_tc<0><<<gridG, 256>>>(rA, rW + 2 * Ec * Ec, qp, 0.125f);

    attn_tc_kernel<<<dim3(Sc / 128, Hc, Bc), 256, ATTN_SMEM_BYTES>>>();

    gemm_tc<1><<<gridG, 256>>>(ctx, rW + 3 * Ec * Ec, out, 1.0f);
}

// round 6
// speedup vs baseline: 7.4243x; 1.8937x over previous
#include <cuda_runtime.h>
#include <cuda_fp16.h>
#include <math.h>
#include <stdint.h>

// Problem constants
#define Bc 4
#define Sc 2048
#define Ec 1024
#define Hc 16
#define Dc 64
#define Mtot (Bc*Sc)   // 8192
#define Kdim 1024

// GEMM tiling (fp16)
#define MT 128
#define NT 128
#define KT 32
#define KTILES (Kdim/KT)   // 32
#define GP 40              // smem pitch in halves (conflict-free)

// Scratch (allocation-free: __device__ globals)
__device__ __half g_kp[Bc*Hc*Sc*Dc];   // [B,H,S,D]
__device__ __half g_vp[Bc*Hc*Sc*Dc];
__device__ __half g_qp[Bc*Hc*Sc*Dc];   // pre-scaled by 1/8
__device__ __half g_ctx[Bc*Sc*Ec];     // [B,S,E]
__device__ __half g_rA[Mtot*Kdim];     // converted activation (reused k,v,q)
__device__ __half g_rW[4*Ec*Ec];       // converted weights

// ---------------------------------------------------------------------------
// helpers
// ---------------------------------------------------------------------------
__device__ __forceinline__ uint32_t smem_u32(const void* p) {
    uint32_t a;
    asm("{ .reg .u64 t; cvta.to.shared.u64 t, %1; cvt.u32.u64 %0, t; }" : "=r"(a) : "l"(p));
    return a;
}
#define CP_ASYNC16(dst, src) \
    asm volatile("cp.async.cg.shared.global [%0], [%1], 16;" :: "r"(dst), "l"(src))
#define CP_COMMIT() asm volatile("cp.async.commit_group;" ::: "memory")
#define CP_WAIT(n)  asm volatile("cp.async.wait_group %0;" :: "n"(n) : "memory")

#define MMA_F16(d, a, b) \
    asm volatile("mma.sync.aligned.m16n8k16.row.col.f32.f16.f16.f32 " \
        "{%0,%1,%2,%3}, {%4,%5,%6,%7}, {%8,%9}, {%0,%1,%2,%3};" \
        : "+f"((d)[0]), "+f"((d)[1]), "+f"((d)[2]), "+f"((d)[3]) \
        : "r"((a)[0]), "r"((a)[1]), "r"((a)[2]), "r"((a)[3]), \
          "r"((b)[0]), "r"((b)[1]))

#define LDMATRIX_X4_TRANS(r0, r1, r2, r3, addr) \
    asm volatile("ldmatrix.sync.aligned.m8n8.x4.trans.shared.b16 {%0,%1,%2,%3}, [%4];" \
        : "=r"(r0), "=r"(r1), "=r"(r2), "=r"(r3) : "r"(addr))

__device__ __forceinline__ uint32_t h2u(__half2 h) { return *(uint32_t*)&h; }

// ---------------------------------------------------------------------------
// fp32 -> fp16 convert (RNE), 8 elements/thread
// ---------------------------------------------------------------------------
__global__ __launch_bounds__(256) void cvt_half_kernel(const float4* __restrict__ in,
                                                       uint4* __restrict__ out, int n8) {
    int i = blockIdx.x * blockDim.x + threadIdx.x;
    if (i >= n8) return;
    float4 a = in[2 * i], b = in[2 * i + 1];
    uint4 r;
    r.x = h2u(__floats2half2_rn(a.x, a.y));
    r.y = h2u(__floats2half2_rn(a.z, a.w));
    r.z = h2u(__floats2half2_rn(b.x, b.y));
    r.w = h2u(__floats2half2_rn(b.z, b.w));
    out[i] = r;
}

// ---------------------------------------------------------------------------
// fp16 mma.sync GEMM: C[M,N] = A[M,K] @ W[N,K]^T   (M=8192, N=K=1024)
// LAYOUT 0: scatter half into [B,H,S,D] with scale; LAYOUT 1: plain fp32 [M,N]
// ---------------------------------------------------------------------------
template <int LAYOUT>
__global__ __launch_bounds__(256, 2) void gemm_f16(const __half* __restrict__ A,
                                                   const __half* __restrict__ W,
                                                   void* __restrict__ Cout, float scale)
{
    __shared__ __half As[2][MT][GP];
    __shared__ __half Bs[2][NT][GP];

    const int tid  = threadIdx.x;
    const int wid  = tid >> 5;
    const int lane = tid & 31;
    const int warp_m = wid & 1;       // 0..1 (64 rows)
    const int warp_n = wid >> 1;      // 0..3 (32 cols)
    const int fr = lane >> 2;
    const int fc = lane & 3;

    const int n0 = blockIdx.x * NT;
    const int m0 = blockIdx.y * MT;

    // per tile: 128 rows x 32 halves = 4 chunks of 8 halves per row -> 512 per matrix
    auto load_tile = [&](int kt, int buf) {
        const int k0 = kt * KT;
        #pragma unroll
        for (int i = 0; i < 2; i++) {
            int c = tid + i * 256;
            int row = c >> 2, seg = c & 3;
            CP_ASYNC16(smem_u32(&As[buf][row][seg * 8]),
                       A + (size_t)(m0 + row) * Kdim + k0 + seg * 8);
            CP_ASYNC16(smem_u32(&Bs[buf][row][seg * 8]),
                       W + (size_t)(n0 + row) * Kdim + k0 + seg * 8);
        }
    };

    float acc[4][4][4];
    #pragma unroll
    for (int i = 0; i < 4; i++)
        #pragma unroll
        for (int j = 0; j < 4; j++)
            #pragma unroll
            for (int r = 0; r < 4; r++) acc[i][j][r] = 0.0f;

    load_tile(0, 0);
    CP_COMMIT();

    for (int kt = 0; kt < KTILES; kt++) {
        const int buf = kt & 1;
        if (kt + 1 < KTILES) {
            load_tile(kt + 1, buf ^ 1);
            CP_COMMIT();
            CP_WAIT(1);
        } else {
            CP_WAIT(0);
        }
        __syncthreads();

        #pragma unroll
        for (int ks = 0; ks < KT; ks += 16) {
            uint32_t af[4][4], bf[4][2];
            #pragma unroll
            for (int mt = 0; mt < 4; mt++) {
                int row = warp_m * 64 + mt * 16 + fr;
                af[mt][0] = *(const uint32_t*)&As[buf][row    ][ks + 2 * fc];
                af[mt][1] = *(const uint32_t*)&As[buf][row + 8][ks + 2 * fc];
                af[mt][2] = *(const uint32_t*)&As[buf][row    ][ks + 2 * fc + 8];
                af[mt][3] = *(const uint32_t*)&As[buf][row + 8][ks + 2 * fc + 8];
            }
            #pragma unroll
            for (int nt = 0; nt < 4; nt++) {
                int col = warp_n * 32 + nt * 8 + fr;
                bf[nt][0] = *(const uint32_t*)&Bs[buf][col][ks + 2 * fc];
                bf[nt][1] = *(const uint32_t*)&Bs[buf][col][ks + 2 * fc + 8];
            }
            #pragma unroll
            for (int mt = 0; mt < 4; mt++)
                #pragma unroll
                for (int nt = 0; nt < 4; nt++)
                    MMA_F16(acc[mt][nt], af[mt], bf[nt]);
        }
        __syncthreads();
    }

    #pragma unroll
    for (int mt = 0; mt < 4; mt++) {
        #pragma unroll
        for (int nt = 0; nt < 4; nt++) {
            int n = n0 + warp_n * 32 + nt * 8 + fc * 2;
            #pragma unroll
            for (int half_i = 0; half_i < 2; half_i++) {
                int m = m0 + warp_m * 64 + mt * 16 + fr + half_i * 8;
                float v0 = acc[mt][nt][half_i * 2];
                float v1 = acc[mt][nt][half_i * 2 + 1];
                if (LAYOUT == 1) {
                    *(float2*)&((float*)Cout)[(size_t)m * Ec + n] = make_float2(v0, v1);
                } else {
                    int b = m >> 11, s = m & 2047;
                    int h = n >> 6,  d = n & 63;
                    __half2 hv = __floats2half2_rn(v0 * scale, v1 * scale);
                    *(__half2*)&((__half*)Cout)[(size_t)(((b * Hc + h) * Sc) + s) * Dc + d] = hv;
                }
            }
        }
    }
}

// ---------------------------------------------------------------------------
// Tensor-core flash attention (causal), fp16 mma.sync (fp32 accum).
// Block: 128 queries x (b,h); 8 warps (m16 each). Key tiles of 64.
// smem halves: Ks[2][64][72] @0 ; Vs[2][64][72] @9216 ; Pq[128][72] @18432
// ---------------------------------------------------------------------------
#define ATTN_SMEM_BYTES ((9216 + 9216 + 9216) * 2)   // 55296

__global__ __launch_bounds__(256) void attn_tc_kernel()
{
    extern __shared__ __half sh[];
    const int tid  = threadIdx.x;
    const int wq   = tid >> 5;
    const int lane = tid & 31;
    const int fr   = lane >> 2;
    const int fc   = lane & 3;
    const int b    = blockIdx.z;
    const int h    = blockIdx.y;
    const int qb   = (int)(gridDim.x - 1 - blockIdx.x);   // heavy tiles first

    const size_t bh = (size_t)(b * Hc + h) * Sc;
    const __half* kg = g_kp + bh * Dc;
    const __half* vg = g_vp + bh * Dc;

    __half* Ks = sh;                    // [2][64][72]
    __half* Pq = sh + 18432;            // [128][72] (Q stage / per-warp P)
    __half* Pw = Pq + wq * 16 * 72;
    const uint32_t smb = smem_u32(sh);

    // ---- stage Q tile (128 x 64 halves) ----
    {
        const __half* qg = g_qp + (bh + (size_t)qb * 128) * Dc;
        #pragma unroll
        for (int i = 0; i < 4; i++) {
            int c = tid + i * 256;          // 0..1023
            int row = c >> 3, seg = c & 7;
            CP_ASYNC16(smb + (uint32_t)(18432 + row * 72 + seg * 8) * 2,
                       qg + (size_t)row * 64 + seg * 8);
        }
        CP_COMMIT(); CP_WAIT(0);
    }
    __syncthreads();

    // Q a-frags for 4 k16-steps
    uint32_t qa[4][4];
    #pragma unroll
    for (int s = 0; s < 4; s++) {
        qa[s][0] = *(const uint32_t*)&Pw[fr * 72 + s * 16 + 2 * fc];
        qa[s][1] = *(const uint32_t*)&Pw[(fr + 8) * 72 + s * 16 + 2 * fc];
        qa[s][2] = *(const uint32_t*)&Pw[fr * 72 + s * 16 + 2 * fc + 8];
        qa[s][3] = *(const uint32_t*)&Pw[(fr + 8) * 72 + s * 16 + 2 * fc + 8];
    }

    float o[8][4];
    #pragma unroll
    for (int i = 0; i < 8; i++)
        #pragma unroll
        for (int j = 0; j < 4; j++) o[i][j] = 0.0f;
    float m0 = -INFINITY, m1 = -INFINITY, l0 = 0.0f, l1 = 0.0f;

    const int qrow  = qb * 128 + wq * 16 + fr;
    const int qwmin = qb * 128 + wq * 16;
    const int qwmax = qwmin + 15;
    const int cnt   = 2 * qb + 2;

    auto stage_kv = [&](int kt, int buf) {
        const __half* kk = kg + (size_t)(kt * 64) * 64;
        const __half* vv = vg + (size_t)(kt * 64) * 64;
        #pragma unroll
        for (int i = 0; i < 2; i++) {
            int c = tid + i * 256;          // 0..511
            int row = c >> 3, seg = c & 7;
            CP_ASYNC16(smb + (uint32_t)(buf * 4608 + row * 72 + seg * 8) * 2,
                       kk + (size_t)row * 64 + seg * 8);
            CP_ASYNC16(smb + (uint32_t)(9216 + buf * 4608 + row * 72 + seg * 8) * 2,
                       vv + (size_t)row * 64 + seg * 8);
        }
    };

    stage_kv(0, 0);
    CP_COMMIT();

    for (int kt = 0; kt < cnt; kt++) {
        const int buf = kt & 1;
        if (kt + 1 < cnt) {
            stage_kv(kt + 1, buf ^ 1);
            CP_COMMIT();
            CP_WAIT(1);
        } else {
            CP_WAIT(0);
        }
        __syncthreads();

        if (kt * 64 <= qwmax) {
            const __half* Kb = Ks + buf * 4608;
            const uint32_t vb_base = smb + (uint32_t)(9216 + buf * 4608) * 2;

            // S = Q K^T  (16 x 64 per warp), 4 k16-steps over D
            float sc[8][4];
            #pragma unroll
            for (int nt = 0; nt < 8; nt++) {
                sc[nt][0] = sc[nt][1] = sc[nt][2] = sc[nt][3] = 0.0f;
                #pragma unroll
                for (int s = 0; s < 4; s++) {
                    uint32_t bb[2];
                    bb[0] = *(const uint32_t*)&Kb[(nt * 8 + fr) * 72 + s * 16 + 2 * fc];
                    bb[1] = *(const uint32_t*)&Kb[(nt * 8 + fr) * 72 + s * 16 + 2 * fc + 8];
                    MMA_F16(sc[nt], qa[s], bb);
                }
            }

            // causal mask
            if (kt * 64 + 63 > qwmin) {
                #pragma unroll
                for (int nt = 0; nt < 8; nt++) {
                    int colb = kt * 64 + nt * 8 + 2 * fc;
                    if (colb     > qrow)     sc[nt][0] = -1e30f;
                    if (colb + 1 > qrow)     sc[nt][1] = -1e30f;
                    if (colb     > qrow + 8) sc[nt][2] = -1e30f;
                    if (colb + 1 > qrow + 8) sc[nt][3] = -1e30f;
                }
            }

            // row maxes
            float t0 = -1e30f, t1 = -1e30f;
            #pragma unroll
            for (int nt = 0; nt < 8; nt++) {
                t0 = fmaxf(t0, fmaxf(sc[nt][0], sc[nt][1]));
                t1 = fmaxf(t1, fmaxf(sc[nt][2], sc[nt][3]));
            }
            t0 = fmaxf(t0, __shfl_xor_sync(0xffffffffu, t0, 1));
            t0 = fmaxf(t0, __shfl_xor_sync(0xffffffffu, t0, 2));
            t1 = fmaxf(t1, __shfl_xor_sync(0xffffffffu, t1, 1));
            t1 = fmaxf(t1, __shfl_xor_sync(0xffffffffu, t1, 2));

            float mn0 = fmaxf(m0, t0), mn1 = fmaxf(m1, t1);
            float c0 = __expf(m0 - mn0), c1 = __expf(m1 - mn1);
            l0 *= c0; l1 *= c1;
            #pragma unroll
            for (int nd = 0; nd < 8; nd++) {
                o[nd][0] *= c0; o[nd][1] *= c0;
                o[nd][2] *= c1; o[nd][3] *= c1;
            }
            m0 = mn0; m1 = mn1;

            // P = exp(S - m) -> half, stash per-warp
            #pragma unroll
            for (int nt = 0; nt < 8; nt++) {
                float p0 = __expf(sc[nt][0] - m0);
                float p1 = __expf(sc[nt][1] - m0);
                float p2 = __expf(sc[nt][2] - m1);
                float p3 = __expf(sc[nt][3] - m1);
                __half2 h01 = __floats2half2_rn(p0, p1);
                __half2 h23 = __floats2half2_rn(p2, p3);
                // accumulate l from the rounded values (matches what PV uses)
                float2 f01 = __half22float2(h01);
                float2 f23 = __half22float2(h23);
                l0 += f01.x + f01.y; l1 += f23.x + f23.y;
                *(__half2*)&Pw[fr * 72 + nt * 8 + 2 * fc]       = h01;
                *(__half2*)&Pw[(fr + 8) * 72 + nt * 8 + 2 * fc] = h23;
            }
            __syncwarp();

            // O += P V : A = P (k=key), B = V via ldmatrix.x4.trans
            #pragma unroll
            for (int s = 0; s < 4; s++) {       // key blocks of 16
                uint32_t pa[4];
                pa[0] = *(const uint32_t*)&Pw[fr * 72 + s * 16 + 2 * fc];
                pa[1] = *(const uint32_t*)&Pw[(fr + 8) * 72 + s * 16 + 2 * fc];
                pa[2] = *(const uint32_t*)&Pw[fr * 72 + s * 16 + 2 * fc + 8];
                pa[3] = *(const uint32_t*)&Pw[(fr + 8) * 72 + s * 16 + 2 * fc + 8];
                #pragma unroll
                for (int ndp = 0; ndp < 4; ndp++) {   // 16 d-cols per ldmatrix.x4
                    uint32_t addr = vb_base +
                        (uint32_t)((s * 16 + (lane & 15)) * 72 + ndp * 16 + (lane >> 4) * 8) * 2;
                    uint32_t r0, r1, r2, r3;
                    LDMATRIX_X4_TRANS(r0, r1, r2, r3, addr);
                    uint32_t b0[2] = {r0, r1};
                    uint32_t b1[2] = {r2, r3};
                    MMA_F16(o[2 * ndp],     pa, b0);
                    MMA_F16(o[2 * ndp + 1], pa, b1);
                }
            }
        }
        __syncthreads();
    }

    // epilogue
    l0 += __shfl_xor_sync(0xffffffffu, l0, 1);
    l0 += __shfl_xor_sync(0xffffffffu, l0, 2);
    l1 += __shfl_xor_sync(0xffffffffu, l1, 1);
    l1 += __shfl_xor_sync(0xffffffffu, l1, 2);
    const float inv0 = 1.0f / l0;
    const float inv1 = 1.0f / l1;

    __half* ctx0 = g_ctx + ((size_t)b * Sc + qrow) * Ec + h * Dc;
    __half* ctx1 = g_ctx + ((size_t)b * Sc + qrow + 8) * Ec + h * Dc;
    #pragma unroll
    for (int nd = 0; nd < 8; nd++) {
        int col = nd * 8 + 2 * fc;
        *(__half2*)&ctx0[col] = __floats2half2_rn(o[nd][0] * inv0, o[nd][1] * inv0);
        *(__half2*)&ctx1[col] = __floats2half2_rn(o[nd][2] * inv1, o[nd][3] * inv1);
    }
}

// ---------------------------------------------------------------------------
// Launch
// ---------------------------------------------------------------------------
extern "C" void kernel_launch(void* const* d_in, const int* in_sizes, int n_in,
                              void* d_out, int out_size)
{
    const float* k  = (const float*)d_in[0];
    const float* v  = (const float*)d_in[1];
    const float* q  = (const float*)d_in[2];
    const float* Wk = (const float*)d_in[3];
    const float* Wv = (const float*)d_in[4];
    const float* Wq = (const float*)d_in[5];
    const float* Wo = (const float*)d_in[6];
    float* out = (float*)d_out;

    __half* rA = nullptr; cudaGetSymbolAddress((void**)&rA, g_rA);
    __half* rW = nullptr; cudaGetSymbolAddress((void**)&rW, g_rW);
    __half* kp = nullptr; cudaGetSymbolAddress((void**)&kp, g_kp);
    __half* vp = nullptr; cudaGetSymbolAddress((void**)&vp, g_vp);
    __half* qp = nullptr; cudaGetSymbolAddress((void**)&qp, g_qp);
    __half* ctx = nullptr; cudaGetSymbolAddress((void**)&ctx, g_ctx);

    cudaFuncSetAttribute(attn_tc_kernel, cudaFuncAttributeMaxDynamicSharedMemorySize,
                         ATTN_SMEM_BYTES);

    const int nW8 = Ec * Ec / 8;      // 131072
    const int nA8 = Mtot * Ec / 8;    // 1048576

    cvt_half_kernel<<<nW8 / 256, 256>>>((const float4*)Wk, (uint4*)(rW + 0 * Ec * Ec), nW8);
    cvt_half_kernel<<<nW8 / 256, 256>>>((const float4*)Wv, (uint4*)(rW + 1 * Ec * Ec), nW8);
    cvt_half_kernel<<<nW8 / 256, 256>>>((const float4*)Wq, (uint4*)(rW + 2 * Ec * Ec), nW8);
    cvt_half_kernel<<<nW8 / 256, 256>>>((const float4*)Wo, (uint4*)(rW + 3 * Ec * Ec), nW8);

    dim3 gridG(Ec / NT, Mtot / MT);   // (8, 64)

    cvt_half_kernel<<<nA8 / 256, 256>>>((const float4*)k, (uint4*)rA, nA8);
    gemm_f16<0><<<gridG, 256>>>(rA, rW + 0 * Ec * Ec, kp, 1.0f);

    cvt_half_kernel<<<nA8 / 256, 256>>>((const float4*)v, (uint4*)rA, nA8);
    gemm_f16<0><<<gridG, 256>>>(rA, rW + 1 * Ec * Ec, vp, 1.0f);

    cvt_half_kernel<<<nA8 / 256, 256>>>((const float4*)q, (uint4*)rA, nA8);
    gemm_f16<0><<<gridG, 256>>>(rA, rW + 2 * Ec * Ec, qp, 0.125f);

    attn_tc_kernel<<<dim3(Sc / 128, Hc, Bc), 256, ATTN_SMEM_BYTES>>>();

    gemm_f16<1><<<gridG, 256>>>(ctx, rW + 3 * Ec * Ec, out, 1.0f);
}

// round 7
// speedup vs baseline: 7.9303x; 1.0681x over previous
#include <cuda_runtime.h>
#include <cuda_fp16.h>
#include <math.h>
#include <stdint.h>

// Problem constants
#define Bc 4
#define Sc 2048
#define Ec 1024
#define Hc 16
#define Dc 64
#define Mtot (Bc*Sc)   // 8192
#define Kdim 1024

// GEMM tiling
#define MT 128
#define NT 128
#define KT 32
#define KTILES (Kdim/KT)   // 32

// QKV gemm dynamic smem layout (bytes): A fp32 pitch 40 floats, B fp16 pitch 40 halves
#define QKV_A_BUF  20480                 // 128*40*4
#define QKV_B_OFF  40960                 // 2 A buffers
#define QKV_B_BUF  10240                 // 128*40*2
#define QKV_SMEM   61440

// Scratch (allocation-free: __device__ globals)
__device__ __half g_kp[Bc*Hc*Sc*Dc];   // [B,H,S,D]
__device__ __half g_vp[Bc*Hc*Sc*Dc];
__device__ __half g_qp[Bc*Hc*Sc*Dc];   // pre-scaled by 1/8
__device__ __half g_ctx[Bc*Sc*Ec];     // [B,S,E]
__device__ __half g_rW[4*Ec*Ec];       // converted weights

// ---------------------------------------------------------------------------
// helpers
// ---------------------------------------------------------------------------
__device__ __forceinline__ uint32_t smem_u32(const void* p) {
    uint32_t a;
    asm("{ .reg .u64 t; cvta.to.shared.u64 t, %1; cvt.u32.u64 %0, t; }" : "=r"(a) : "l"(p));
    return a;
}
#define CP_ASYNC16(dst, src) \
    asm volatile("cp.async.cg.shared.global [%0], [%1], 16;" :: "r"(dst), "l"(src))
#define CP_COMMIT() asm volatile("cp.async.commit_group;" ::: "memory")
#define CP_WAIT(n)  asm volatile("cp.async.wait_group %0;" :: "n"(n) : "memory")

#define MMA_F16(d, a, b) \
    asm volatile("mma.sync.aligned.m16n8k16.row.col.f32.f16.f16.f32 " \
        "{%0,%1,%2,%3}, {%4,%5,%6,%7}, {%8,%9}, {%0,%1,%2,%3};" \
        : "+f"((d)[0]), "+f"((d)[1]), "+f"((d)[2]), "+f"((d)[3]) \
        : "r"((a)[0]), "r"((a)[1]), "r"((a)[2]), "r"((a)[3]), \
          "r"((b)[0]), "r"((b)[1]))

#define LDMATRIX_X4(r0, r1, r2, r3, addr) \
    asm volatile("ldmatrix.sync.aligned.m8n8.x4.shared.b16 {%0,%1,%2,%3}, [%4];" \
        : "=r"(r0), "=r"(r1), "=r"(r2), "=r"(r3) : "r"(addr))

#define LDMATRIX_X4_TRANS(r0, r1, r2, r3, addr) \
    asm volatile("ldmatrix.sync.aligned.m8n8.x4.trans.shared.b16 {%0,%1,%2,%3}, [%4];" \
        : "=r"(r0), "=r"(r1), "=r"(r2), "=r"(r3) : "r"(addr))

__device__ __forceinline__ uint32_t h2u(__half2 h) { return *(uint32_t*)&h; }

// ---------------------------------------------------------------------------
// fused weight convert: 4 weights fp32 -> fp16
// ---------------------------------------------------------------------------
#define NW8 (Ec*Ec/8)   // 131072 8-elt chunks per weight
__global__ __launch_bounds__(256) void cvt_weights_kernel(const float4* __restrict__ w0,
                                                          const float4* __restrict__ w1,
                                                          const float4* __restrict__ w2,
                                                          const float4* __restrict__ w3) {
    int i = blockIdx.x * blockDim.x + threadIdx.x;     // 0 .. 4*NW8-1
    int w = i >> 17;                                    // / NW8
    int idx = i & (NW8 - 1);
    const float4* src = (w == 0) ? w0 : (w == 1) ? w1 : (w == 2) ? w2 : w3;
    float4 a = src[2 * idx], b = src[2 * idx + 1];
    uint4 r;
    r.x = h2u(__floats2half2_rn(a.x, a.y));
    r.y = h2u(__floats2half2_rn(a.z, a.w));
    r.z = h2u(__floats2half2_rn(b.x, b.y));
    r.w = h2u(__floats2half2_rn(b.z, b.w));
    ((uint4*)(g_rW + (size_t)w * Ec * Ec))[idx] = r;
}

// ---------------------------------------------------------------------------
// Fused QKV GEMM: z selects (k,Wk)->g_kp, (v,Wv)->g_vp, (q,Wq)->g_qp(*0.125).
// A read as fp32, converted to fp16 in registers. B fp16, frags via ldmatrix.
// ---------------------------------------------------------------------------
__global__ __launch_bounds__(256, 2) void gemm_qkv(const float* __restrict__ Ak,
                                                   const float* __restrict__ Av,
                                                   const float* __restrict__ Aq)
{
    extern __shared__ char smc[];
    float*  Asf = (float*)smc;                          // [2][128][40]
    const uint32_t smb  = smem_u32(smc);
    const uint32_t smbB = smb + QKV_B_OFF;

    const int tid  = threadIdx.x;
    const int wid  = tid >> 5;
    const int lane = tid & 31;
    const int warp_m = wid & 1;
    const int warp_n = wid >> 1;
    const int fr = lane >> 2;
    const int fc = lane & 3;
    const int l16 = lane & 15;
    const int lh  = lane >> 4;

    const int z  = blockIdx.z;
    const int n0 = blockIdx.x * NT;
    const int m0 = blockIdx.y * MT;

    const float* A = (z == 0) ? Ak : (z == 1) ? Av : Aq;
    const __half* W = g_rW + (size_t)z * Ec * Ec;
    __half* outp = (z == 0) ? g_kp : (z == 1) ? g_vp : g_qp;
    const float scale = (z == 2) ? 0.125f : 1.0f;

    auto load_tile = [&](int kt, int buf) {
        const int k0 = kt * KT;
        #pragma unroll
        for (int i = 0; i < 4; i++) {                   // A: 1024 chunks
            int c = tid + i * 256;
            int row = c >> 3, seg = c & 7;
            CP_ASYNC16(smb + buf * QKV_A_BUF + row * 160 + seg * 16,
                       A + (size_t)(m0 + row) * Kdim + k0 + seg * 4);
        }
        #pragma unroll
        for (int i = 0; i < 2; i++) {                   // B: 512 chunks
            int c = tid + i * 256;
            int row = c >> 2, seg = c & 3;
            CP_ASYNC16(smbB + buf * QKV_B_BUF + row * 80 + seg * 16,
                       W + (size_t)(n0 + row) * Kdim + k0 + seg * 8);
        }
    };

    float acc[4][4][4];
    #pragma unroll
    for (int i = 0; i < 4; i++)
        #pragma unroll
        for (int j = 0; j < 4; j++)
            #pragma unroll
            for (int r = 0; r < 4; r++) acc[i][j][r] = 0.0f;

    load_tile(0, 0);
    CP_COMMIT();

    for (int kt = 0; kt < KTILES; kt++) {
        const int buf = kt & 1;
        if (kt + 1 < KTILES) {
            load_tile(kt + 1, buf ^ 1);
            CP_COMMIT();
            CP_WAIT(1);
        } else {
            CP_WAIT(0);
        }
        __syncthreads();

        const float* Ab = Asf + buf * (128 * 40);
        #pragma unroll
        for (int ks = 0; ks < KT; ks += 16) {
            uint32_t af[4][4], bf[4][2];
            #pragma unroll
            for (int mt = 0; mt < 4; mt++) {
                int row = warp_m * 64 + mt * 16 + fr;
                float2 f0 = *(const float2*)&Ab[row * 40 + ks + 2 * fc];
                float2 f1 = *(const float2*)&Ab[(row + 8) * 40 + ks + 2 * fc];
                float2 f2 = *(const float2*)&Ab[row * 40 + ks + 2 * fc + 8];
                float2 f3 = *(const float2*)&Ab[(row + 8) * 40 + ks + 2 * fc + 8];
                af[mt][0] = h2u(__floats2half2_rn(f0.x, f0.y));
                af[mt][1] = h2u(__floats2half2_rn(f1.x, f1.y));
                af[mt][2] = h2u(__floats2half2_rn(f2.x, f2.y));
                af[mt][3] = h2u(__floats2half2_rn(f3.x, f3.y));
            }
            #pragma unroll
            for (int np = 0; np < 2; np++) {
                uint32_t r0, r1, r2, r3;
                uint32_t addr = smbB + buf * QKV_B_BUF +
                    (uint32_t)(warp_n * 32 + np * 16 + l16) * 80 + (uint32_t)(ks + lh * 8) * 2;
                LDMATRIX_X4(r0, r1, r2, r3, addr);
                bf[2 * np][0] = r0; bf[2 * np][1] = r2;
                bf[2 * np + 1][0] = r1; bf[2 * np + 1][1] = r3;
            }
            #pragma unroll
            for (int mt = 0; mt < 4; mt++)
                #pragma unroll
                for (int nt = 0; nt < 4; nt++)
                    MMA_F16(acc[mt][nt], af[mt], bf[nt]);
        }
        __syncthreads();
    }

    // scatter epilogue: half2 into [B,H,S,D]
    #pragma unroll
    for (int mt = 0; mt < 4; mt++) {
        #pragma unroll
        for (int nt = 0; nt < 4; nt++) {
            int n = n0 + warp_n * 32 + nt * 8 + fc * 2;
            #pragma unroll
            for (int hi = 0; hi < 2; hi++) {
                int m = m0 + warp_m * 64 + mt * 16 + fr + hi * 8;
                int b = m >> 11, s = m & 2047;
                int h = n >> 6,  d = n & 63;
                __half2 hv = __floats2half2_rn(acc[mt][nt][hi * 2] * scale,
                                               acc[mt][nt][hi * 2 + 1] * scale);
                *(__half2*)&outp[(size_t)(((b * Hc + h) * Sc) + s) * Dc + d] = hv;
            }
        }
    }
}

// ---------------------------------------------------------------------------
// Output GEMM: out[M,N] = ctx[M,K](fp16) @ Wo[N,K]^T, fp32 out. ldmatrix both.
// ---------------------------------------------------------------------------
__global__ __launch_bounds__(256, 2) void gemm_out(float* __restrict__ Cout)
{
    __shared__ __half As[2][MT][40];
    __shared__ __half Bs[2][NT][40];

    const int tid  = threadIdx.x;
    const int wid  = tid >> 5;
    const int lane = tid & 31;
    const int warp_m = wid & 1;
    const int warp_n = wid >> 1;
    const int fr = lane >> 2;
    const int fc = lane & 3;
    const int l16 = lane & 15;
    const int lh  = lane >> 4;

    const int n0 = blockIdx.x * NT;
    const int m0 = blockIdx.y * MT;
    const __half* A = g_ctx;
    const __half* W = g_rW + (size_t)3 * Ec * Ec;

    auto load_tile = [&](int kt, int buf) {
        const int k0 = kt * KT;
        #pragma unroll
        for (int i = 0; i < 2; i++) {
            int c = tid + i * 256;
            int row = c >> 2, seg = c & 3;
            CP_ASYNC16(smem_u32(&As[buf][row][seg * 8]),
                       A + (size_t)(m0 + row) * Kdim + k0 + seg * 8);
            CP_ASYNC16(smem_u32(&Bs[buf][row][seg * 8]),
                       W + (size_t)(n0 + row) * Kdim + k0 + seg * 8);
        }
    };

    float acc[4][4][4];
    #pragma unroll
    for (int i = 0; i < 4; i++)
        #pragma unroll
        for (int j = 0; j < 4; j++)
            #pragma unroll
            for (int r = 0; r < 4; r++) acc[i][j][r] = 0.0f;

    load_tile(0, 0);
    CP_COMMIT();

    for (int kt = 0; kt < KTILES; kt++) {
        const int buf = kt & 1;
        if (kt + 1 < KTILES) {
            load_tile(kt + 1, buf ^ 1);
            CP_COMMIT();
            CP_WAIT(1);
        } else {
            CP_WAIT(0);
        }
        __syncthreads();

        #pragma unroll
        for (int ks = 0; ks < KT; ks += 16) {
            uint32_t af[4][4], bf[4][2];
            #pragma unroll
            for (int mt = 0; mt < 4; mt++) {
                uint32_t addr = smem_u32(&As[buf][warp_m * 64 + mt * 16 + l16][ks + lh * 8]);
                LDMATRIX_X4(af[mt][0], af[mt][1], af[mt][2], af[mt][3], addr);
            }
            #pragma unroll
            for (int np = 0; np < 2; np++) {
                uint32_t r0, r1, r2, r3;
                uint32_t addr = smem_u32(&Bs[buf][warp_n * 32 + np * 16 + l16][ks + lh * 8]);
                LDMATRIX_X4(r0, r1, r2, r3, addr);
                bf[2 * np][0] = r0; bf[2 * np][1] = r2;
                bf[2 * np + 1][0] = r1; bf[2 * np + 1][1] = r3;
            }
            #pragma unroll
            for (int mt = 0; mt < 4; mt++)
                #pragma unroll
                for (int nt = 0; nt < 4; nt++)
                    MMA_F16(acc[mt][nt], af[mt], bf[nt]);
        }
        __syncthreads();
    }

    #pragma unroll
    for (int mt = 0; mt < 4; mt++) {
        #pragma unroll
        for (int nt = 0; nt < 4; nt++) {
            int n = n0 + warp_n * 32 + nt * 8 + fc * 2;
            #pragma unroll
            for (int hi = 0; hi < 2; hi++) {
                int m = m0 + warp_m * 64 + mt * 16 + fr + hi * 8;
                *(float2*)&Cout[(size_t)m * Ec + n] =
                    make_float2(acc[mt][nt][hi * 2], acc[mt][nt][hi * 2 + 1]);
            }
        }
    }
}

// ---------------------------------------------------------------------------
// Tensor-core flash attention (causal), fp16 mma.sync (fp32 accum).
// Block: 128 queries x (b,h); 8 warps (m16 each). Key tiles of 64.
// smem halves: Ks[2][64][72] @0 ; Vs[2][64][72] @9216 ; Pq[128][72] @18432
// ---------------------------------------------------------------------------
#define ATTN_SMEM_BYTES ((9216 + 9216 + 9216) * 2)   // 55296

__global__ __launch_bounds__(256) void attn_tc_kernel()
{
    extern __shared__ __half sh[];
    const int tid  = threadIdx.x;
    const int wq   = tid >> 5;
    const int lane = tid & 31;
    const int fr   = lane >> 2;
    const int fc   = lane & 3;
    const int l16  = lane & 15;
    const int lh   = lane >> 4;
    const int b    = blockIdx.z;
    const int h    = blockIdx.y;
    const int qb   = (int)(gridDim.x - 1 - blockIdx.x);   // heavy tiles first

    const size_t bh = (size_t)(b * Hc + h) * Sc;
    const __half* kg = g_kp + bh * Dc;
    const __half* vg = g_vp + bh * Dc;

    __half* Pw = sh + 18432 + wq * 16 * 72;
    const uint32_t smb = smem_u32(sh);
    const uint32_t pw_base = smb + (uint32_t)(18432 + wq * 16 * 72) * 2;

    // ---- stage Q tile (128 x 64 halves) into P region ----
    {
        const __half* qg = g_qp + (bh + (size_t)qb * 128) * Dc;
        #pragma unroll
        for (int i = 0; i < 4; i++) {
            int c = tid + i * 256;
            int row = c >> 3, seg = c & 7;
            CP_ASYNC16(smb + (uint32_t)(18432 + row * 72 + seg * 8) * 2,
                       qg + (size_t)row * 64 + seg * 8);
        }
        CP_COMMIT(); CP_WAIT(0);
    }
    __syncthreads();

    // Q a-frags for 4 k16-steps via ldmatrix
    uint32_t qa[4][4];
    #pragma unroll
    for (int s = 0; s < 4; s++) {
        uint32_t addr = pw_base + (uint32_t)(l16 * 72 + s * 16 + lh * 8) * 2;
        LDMATRIX_X4(qa[s][0], qa[s][1], qa[s][2], qa[s][3], addr);
    }

    float o[8][4];
    #pragma unroll
    for (int i = 0; i < 8; i++)
        #pragma unroll
        for (int j = 0; j < 4; j++) o[i][j] = 0.0f;
    float m0 = -INFINITY, m1 = -INFINITY, l0 = 0.0f, l1 = 0.0f;

    const int qrow  = qb * 128 + wq * 16 + fr;
    const int qwmin = qb * 128 + wq * 16;
    const int qwmax = qwmin + 15;
    const int cnt   = 2 * qb + 2;

    auto stage_kv = [&](int kt, int buf) {
        const __half* kk = kg + (size_t)(kt * 64) * 64;
        const __half* vv = vg + (size_t)(kt * 64) * 64;
        #pragma unroll
        for (int i = 0; i < 2; i++) {
            int c = tid + i * 256;
            int row = c >> 3, seg = c & 7;
            CP_ASYNC16(smb + (uint32_t)(buf * 4608 + row * 72 + seg * 8) * 2,
                       kk + (size_t)row * 64 + seg * 8);
            CP_ASYNC16(smb + (uint32_t)(9216 + buf * 4608 + row * 72 + seg * 8) * 2,
                       vv + (size_t)row * 64 + seg * 8);
        }
    };

    stage_kv(0, 0);
    CP_COMMIT();

    for (int kt = 0; kt < cnt; kt++) {
        const int buf = kt & 1;
        if (kt + 1 < cnt) {
            stage_kv(kt + 1, buf ^ 1);
            CP_COMMIT();
            CP_WAIT(1);
        } else {
            CP_WAIT(0);
        }
        __syncthreads();

        if (kt * 64 <= qwmax) {
            const uint32_t kb_base = smb + (uint32_t)(buf * 4608) * 2;
            const uint32_t vb_base = smb + (uint32_t)(9216 + buf * 4608) * 2;

            // S = Q K^T  (16 x 64 per warp): K b-frags via ldmatrix
            float sc[8][4];
            #pragma unroll
            for (int nt = 0; nt < 8; nt++)
                sc[nt][0] = sc[nt][1] = sc[nt][2] = sc[nt][3] = 0.0f;
            #pragma unroll
            for (int s = 0; s < 4; s++) {
                #pragma unroll
                for (int np = 0; np < 4; np++) {     // n16 blocks over 64 keys
                    uint32_t r0, r1, r2, r3;
                    uint32_t addr = kb_base +
                        (uint32_t)((np * 16 + l16) * 72 + s * 16 + lh * 8) * 2;
                    LDMATRIX_X4(r0, r1, r2, r3, addr);
                    uint32_t b0[2] = {r0, r2};
                    uint32_t b1[2] = {r1, r3};
                    MMA_F16(sc[2 * np],     qa[s], b0);
                    MMA_F16(sc[2 * np + 1], qa[s], b1);
                }
            }

            // causal mask
            if (kt * 64 + 63 > qwmin) {
                #pragma unroll
                for (int nt = 0; nt < 8; nt++) {
                    int colb = kt * 64 + nt * 8 + 2 * fc;
                    if (colb     > qrow)     sc[nt][0] = -1e30f;
                    if (colb + 1 > qrow)     sc[nt][1] = -1e30f;
                    if (colb     > qrow + 8) sc[nt][2] = -1e30f;
                    if (colb + 1 > qrow + 8) sc[nt][3] = -1e30f;
                }
            }

            // row maxes
            float t0 = -1e30f, t1 = -1e30f;
            #pragma unroll
            for (int nt = 0; nt < 8; nt++) {
                t0 = fmaxf(t0, fmaxf(sc[nt][0], sc[nt][1]));
                t1 = fmaxf(t1, fmaxf(sc[nt][2], sc[nt][3]));
            }
            t0 = fmaxf(t0, __shfl_xor_sync(0xffffffffu, t0, 1));
            t0 = fmaxf(t0, __shfl_xor_sync(0xffffffffu, t0, 2));
            t1 = fmaxf(t1, __shfl_xor_sync(0xffffffffu, t1, 1));
            t1 = fmaxf(t1, __shfl_xor_sync(0xffffffffu, t1, 2));

            float mn0 = fmaxf(m0, t0), mn1 = fmaxf(m1, t1);
            float c0 = __expf(m0 - mn0), c1 = __expf(m1 - mn1);
            l0 *= c0; l1 *= c1;
            #pragma unroll
            for (int nd = 0; nd < 8; nd++) {
                o[nd][0] *= c0; o[nd][1] *= c0;
                o[nd][2] *= c1; o[nd][3] *= c1;
            }
            m0 = mn0; m1 = mn1;

            // P = exp(S - m) -> half, stash per-warp
            #pragma unroll
            for (int nt = 0; nt < 8; nt++) {
                float p0 = __expf(sc[nt][0] - m0);
                float p1 = __expf(sc[nt][1] - m0);
                float p2 = __expf(sc[nt][2] - m1);
                float p3 = __expf(sc[nt][3] - m1);
                __half2 h01 = __floats2half2_rn(p0, p1);
                __half2 h23 = __floats2half2_rn(p2, p3);
                float2 f01 = __half22float2(h01);
                float2 f23 = __half22float2(h23);
                l0 += f01.x + f01.y; l1 += f23.x + f23.y;
                *(__half2*)&Pw[fr * 72 + nt * 8 + 2 * fc]       = h01;
                *(__half2*)&Pw[(fr + 8) * 72 + nt * 8 + 2 * fc] = h23;
            }
            __syncwarp();

            // O += P V : P a-frags via ldmatrix, V b-frags via ldmatrix.trans
            #pragma unroll
            for (int s = 0; s < 4; s++) {
                uint32_t pa[4];
                uint32_t paddr = pw_base + (uint32_t)(l16 * 72 + s * 16 + lh * 8) * 2;
                LDMATRIX_X4(pa[0], pa[1], pa[2], pa[3], paddr);
                #pragma unroll
                for (int ndp = 0; ndp < 4; ndp++) {
                    uint32_t addr = vb_base +
                        (uint32_t)((s * 16 + l16) * 72 + ndp * 16 + lh * 8) * 2;
                    uint32_t r0, r1, r2, r3;
                    LDMATRIX_X4_TRANS(r0, r1, r2, r3, addr);
                    uint32_t b0[2] = {r0, r1};
                    uint32_t b1[2] = {r2, r3};
                    MMA_F16(o[2 * ndp],     pa, b0);
                    MMA_F16(o[2 * ndp + 1], pa, b1);
                }
            }
        }
        __syncthreads();
    }

    // epilogue
    l0 += __shfl_xor_sync(0xffffffffu, l0, 1);
    l0 += __shfl_xor_sync(0xffffffffu, l0, 2);
    l1 += __shfl_xor_sync(0xffffffffu, l1, 1);
    l1 += __shfl_xor_sync(0xffffffffu, l1, 2);
    const float inv0 = 1.0f / l0;
    const float inv1 = 1.0f / l1;

    __half* ctx0 = g_ctx + ((size_t)b * Sc + qrow) * Ec + h * Dc;
    __half* ctx1 = g_ctx + ((size_t)b * Sc + qrow + 8) * Ec + h * Dc;
    #pragma unroll
    for (int nd = 0; nd < 8; nd++) {
        int col = nd * 8 + 2 * fc;
        *(__half2*)&ctx0[col] = __floats2half2_rn(o[nd][0] * inv0, o[nd][1] * inv0);
        *(__half2*)&ctx1[col] = __floats2half2_rn(o[nd][2] * inv1, o[nd][3] * inv1);
    }
}

// ---------------------------------------------------------------------------
// Launch
// ---------------------------------------------------------------------------
extern "C" void kernel_launch(void* const* d_in, const int* in_sizes, int n_in,
                              void* d_out, int out_size)
{
    const float* k  = (const float*)d_in[0];
    const float* v  = (const float*)d_in[1];
    const float* q  = (const float*)d_in[2];
    const float* Wk = (const float*)d_in[3];
    const float* Wv = (const float*)d_in[4];
    const float* Wq = (const float*)d_in[5];
    const float* Wo = (const float*)d_in[6];
    float* out = (float*)d_out;

    cudaFuncSetAttribute(gemm_qkv, cudaFuncAttributeMaxDynamicSharedMemorySize, QKV_SMEM);
    cudaFuncSetAttribute(attn_tc_kernel, cudaFuncAttributeMaxDynamicSharedMemorySize,
                         ATTN_SMEM_BYTES);

    cvt_weights_kernel<<<4 * NW8 / 256, 256>>>((const float4*)Wk, (const float4*)Wv,
                                               (const float4*)Wq, (const float4*)Wo);

    gemm_qkv<<<dim3(Ec / NT, Mtot / MT, 3), 256, QKV_SMEM>>>(k, v, q);

    attn_tc_kernel<<<dim3(Sc / 128, Hc, Bc), 256, ATTN_SMEM_BYTES>>>();

    gemm_out<<<dim3(Ec / NT, Mtot / MT), 256>>>(out);
}